// round 1
// baseline (speedup 1.0000x reference)
#include <cuda_runtime.h>

// Problem constants (fixed shapes from reference)
#define BATCH   4
#define NPIX    4096          // H*W = 64*64
#define CCH     256
#define GRP     8
#define GSIZE   32            // CCH / GRP
#define MALL    16384         // BATCH * NPIX

// -------- scratch (static device globals; no allocation) --------
__device__ float g_mean[BATCH * GRP];
__device__ float g_rstd[BATCH * GRP];
__device__ float g_xn[MALL * CCH];
__device__ float g_q [MALL * CCH];
__device__ float g_k [MALL * CCH];
__device__ float g_v [MALL * CCH];
__device__ float g_s [(long long)BATCH * NPIX * NPIX];  // 256 MB scores
__device__ float g_o [MALL * CCH];

// ---------------- GroupNorm statistics: one block per (b,g) ----------------
__global__ void gn_stats(const float* __restrict__ x) {
    int bg = blockIdx.x;            // 0..31
    int b = bg >> 3, g = bg & 7;
    const float* base = x + (long)b * NPIX * CCH + g * GSIZE;
    float s = 0.f, ss = 0.f;
    for (int i = threadIdx.x; i < NPIX * GSIZE; i += blockDim.x) {
        int p = i >> 5, c = i & 31;
        float v = base[(long)p * CCH + c];
        s += v; ss += v * v;
    }
    __shared__ float sh[16];
    #pragma unroll
    for (int o = 16; o > 0; o >>= 1) {
        s  += __shfl_xor_sync(0xffffffffu, s,  o);
        ss += __shfl_xor_sync(0xffffffffu, ss, o);
    }
    int w = threadIdx.x >> 5, l = threadIdx.x & 31;
    if (l == 0) { sh[w] = s; sh[8 + w] = ss; }
    __syncthreads();
    if (threadIdx.x == 0) {
        float S = 0.f, SS = 0.f;
        #pragma unroll
        for (int i = 0; i < 8; i++) { S += sh[i]; SS += sh[8 + i]; }
        const float invn = 1.0f / (NPIX * GSIZE);
        float mean = S * invn;
        float var  = SS * invn - mean * mean;
        g_mean[bg] = mean;
        g_rstd[bg] = rsqrtf(var + 1e-3f);
    }
}

// ---------------- GroupNorm apply (vectorized) ----------------
__global__ void gn_apply(const float* __restrict__ x,
                         const float* __restrict__ gamma,
                         const float* __restrict__ beta) {
    long i4 = (long)blockIdx.x * blockDim.x + threadIdx.x;   // float4 index
    float4 xv = ((const float4*)x)[i4];
    int c0 = (int)(i4 & 63) * 4;        // 64 float4 per channel row
    long row = i4 >> 6;                 // pixel index 0..16383
    int b = (int)(row >> 12);           // /4096
    int bg = b * 8 + (c0 >> 5);
    float m = g_mean[bg], r = g_rstd[bg];
    float4 o;
    o.x = (xv.x - m) * r * gamma[c0 + 0] + beta[c0 + 0];
    o.y = (xv.y - m) * r * gamma[c0 + 1] + beta[c0 + 1];
    o.z = (xv.z - m) * r * gamma[c0 + 2] + beta[c0 + 2];
    o.w = (xv.w - m) * r * gamma[c0 + 3] + beta[c0 + 3];
    ((float4*)g_xn)[i4] = o;
}

// ---------------- Generic tiled SGEMM: C = alpha * A @ B' (+bias)(+resid) ----------------
// A: [M,K] row-major.  TRANS_B ? B:[N,K] (dot over K) : B:[K,N].
// Batched via blockIdx.z with element strides sA/sB/sC. All dims multiples of tile.
template<bool TRANS_B, bool BIAS, bool RESID>
__global__ void __launch_bounds__(256, 4)
gemm64(const float* __restrict__ A, const float* __restrict__ B,
       const float* __restrict__ bias, const float* __restrict__ resid,
       float* __restrict__ C, int M, int N, int K,
       long long sA, long long sB, long long sC, float alpha) {
    const int BM = 64, BN = 64, BK = 16;
    __shared__ float As[BK][BM];
    __shared__ float Bs[BK][BN];

    A += (long long)blockIdx.z * sA;
    B += (long long)blockIdx.z * sB;
    C += (long long)blockIdx.z * sC;

    int tid = threadIdx.x;
    int tx = tid & 15;      // n-direction (x4)
    int ty = tid >> 4;      // m-direction (x4)
    int m0 = blockIdx.y * BM;
    int n0 = blockIdx.x * BN;

    float acc[4][4] = {};

    for (int k0 = 0; k0 < K; k0 += BK) {
        #pragma unroll
        for (int i = 0; i < 4; i++) {
            int idx = tid + i * 256;
            int kk = idx & 15, mm = idx >> 4;
            As[kk][mm] = A[(long)(m0 + mm) * K + k0 + kk];
        }
        if (TRANS_B) {
            #pragma unroll
            for (int i = 0; i < 4; i++) {
                int idx = tid + i * 256;
                int kk = idx & 15, nn = idx >> 4;
                Bs[kk][nn] = B[(long)(n0 + nn) * K + k0 + kk];
            }
        } else {
            #pragma unroll
            for (int i = 0; i < 4; i++) {
                int idx = tid + i * 256;
                int nn = idx & 63, kk = idx >> 6;
                Bs[kk][nn] = B[(long)(k0 + kk) * N + n0 + nn];
            }
        }
        __syncthreads();
        #pragma unroll
        for (int kk = 0; kk < BK; kk++) {
            float4 a4 = *(const float4*)&As[kk][ty * 4];
            float4 b4 = *(const float4*)&Bs[kk][tx * 4];
            float a[4] = {a4.x, a4.y, a4.z, a4.w};
            float b[4] = {b4.x, b4.y, b4.z, b4.w};
            #pragma unroll
            for (int i = 0; i < 4; i++)
                #pragma unroll
                for (int j = 0; j < 4; j++)
                    acc[i][j] += a[i] * b[j];
        }
        __syncthreads();
    }

    int nb = n0 + tx * 4;
    float4 bv = make_float4(0.f, 0.f, 0.f, 0.f);
    if (BIAS) bv = *(const float4*)&bias[nb];
    #pragma unroll
    for (int i = 0; i < 4; i++) {
        long m = m0 + ty * 4 + i;
        long off = m * N + nb;
        float4 r;
        r.x = acc[i][0] * alpha; r.y = acc[i][1] * alpha;
        r.z = acc[i][2] * alpha; r.w = acc[i][3] * alpha;
        if (BIAS) { r.x += bv.x; r.y += bv.y; r.z += bv.z; r.w += bv.w; }
        if (RESID) {
            float4 rv = *(const float4*)&resid[off];
            r.x += rv.x; r.y += rv.y; r.z += rv.z; r.w += rv.w;
        }
        *(float4*)&C[off] = r;
    }
}

// ---------------- Row softmax over width 4096, one block per row ----------------
__global__ void softmax4096(float* __restrict__ S) {
    float4* row = (float4*)(S + (long long)blockIdx.x * 4096);
    int tid = threadIdx.x;   // 256
    float4 v[4];
    float mx = -1e30f;
    #pragma unroll
    for (int i = 0; i < 4; i++) {
        v[i] = row[tid + i * 256];
        mx = fmaxf(mx, fmaxf(fmaxf(v[i].x, v[i].y), fmaxf(v[i].z, v[i].w)));
    }
    __shared__ float sh[8];
    #pragma unroll
    for (int o = 16; o > 0; o >>= 1) mx = fmaxf(mx, __shfl_xor_sync(0xffffffffu, mx, o));
    if ((tid & 31) == 0) sh[tid >> 5] = mx;
    __syncthreads();
    mx = sh[0];
    #pragma unroll
    for (int i = 1; i < 8; i++) mx = fmaxf(mx, sh[i]);

    float sum = 0.f;
    #pragma unroll
    for (int i = 0; i < 4; i++) {
        v[i].x = __expf(v[i].x - mx); v[i].y = __expf(v[i].y - mx);
        v[i].z = __expf(v[i].z - mx); v[i].w = __expf(v[i].w - mx);
        sum += v[i].x + v[i].y + v[i].z + v[i].w;
    }
    __syncthreads();   // sh reuse
    #pragma unroll
    for (int o = 16; o > 0; o >>= 1) sum += __shfl_xor_sync(0xffffffffu, sum, o);
    if ((tid & 31) == 0) sh[tid >> 5] = sum;
    __syncthreads();
    float tot = 0.f;
    #pragma unroll
    for (int i = 0; i < 8; i++) tot += sh[i];
    float inv = 1.0f / tot;
    #pragma unroll
    for (int i = 0; i < 4; i++) {
        v[i].x *= inv; v[i].y *= inv; v[i].z *= inv; v[i].w *= inv;
        row[tid + i * 256] = v[i];
    }
}

// ---------------- launch ----------------
extern "C" void kernel_launch(void* const* d_in, const int* in_sizes, int n_in,
                              void* d_out, int out_size) {
    const float* x     = (const float*)d_in[0];
    const float* gamma = (const float*)d_in[1];
    const float* beta  = (const float*)d_in[2];
    const float* wq    = (const float*)d_in[3];
    const float* bq    = (const float*)d_in[4];
    const float* wk    = (const float*)d_in[5];
    const float* bk    = (const float*)d_in[6];
    const float* wv    = (const float*)d_in[7];
    const float* bv    = (const float*)d_in[8];
    const float* wp    = (const float*)d_in[9];
    const float* bp    = (const float*)d_in[10];
    float* out = (float*)d_out;

    float *xn, *q, *k, *v, *s, *o;
    cudaGetSymbolAddress((void**)&xn, g_xn);
    cudaGetSymbolAddress((void**)&q,  g_q);
    cudaGetSymbolAddress((void**)&k,  g_k);
    cudaGetSymbolAddress((void**)&v,  g_v);
    cudaGetSymbolAddress((void**)&s,  g_s);
    cudaGetSymbolAddress((void**)&o,  g_o);

    // 1. GroupNorm
    gn_stats<<<BATCH * GRP, 256>>>(x);
    gn_apply<<<(MALL * CCH / 4) / 256, 256>>>(x, gamma, beta);

    // 2. QKV projections:  [16384,256] @ [256,256]
    gemm64<false, true, false><<<dim3(CCH / 64, MALL / 64, 1), 256>>>(
        xn, wq, bq, nullptr, q, MALL, CCH, CCH, 0, 0, 0, 1.0f);
    gemm64<false, true, false><<<dim3(CCH / 64, MALL / 64, 1), 256>>>(
        xn, wk, bk, nullptr, k, MALL, CCH, CCH, 0, 0, 0, 1.0f);
    gemm64<false, true, false><<<dim3(CCH / 64, MALL / 64, 1), 256>>>(
        xn, wv, bv, nullptr, v, MALL, CCH, CCH, 0, 0, 0, 1.0f);

    // 3. scores = Q @ K^T * 1/16   (per batch, NT)
    gemm64<true, false, false><<<dim3(NPIX / 64, NPIX / 64, BATCH), 256>>>(
        q, k, nullptr, nullptr, s, NPIX, NPIX, CCH,
        (long long)NPIX * CCH, (long long)NPIX * CCH,
        (long long)NPIX * NPIX, 0.0625f);

    // 4. softmax rows
    softmax4096<<<BATCH * NPIX, 256>>>(s);

    // 5. O = attn @ V   (per batch, NN, K = 4096)
    gemm64<false, false, false><<<dim3(CCH / 64, NPIX / 64, BATCH), 256>>>(
        s, v, nullptr, nullptr, o, NPIX, CCH, NPIX,
        (long long)NPIX * NPIX, (long long)NPIX * CCH,
        (long long)NPIX * CCH, 1.0f);

    // 6. y = x + O @ wp + bp
    gemm64<false, true, true><<<dim3(CCH / 64, MALL / 64, 1), 256>>>(
        o, wp, bp, x, out, MALL, CCH, CCH, 0, 0, 0, 1.0f);
}

// round 2
// speedup vs baseline: 4.5090x; 4.5090x over previous
#include <cuda_runtime.h>

// Problem constants (fixed shapes from reference)
#define BATCH   4
#define NPIX    4096          // H*W = 64*64
#define CCH     256
#define GRP     8
#define GSIZE   32            // CCH / GRP
#define MALL    16384         // BATCH * NPIX

// -------- scratch (static device globals; no allocation) --------
__device__ float g_mean[BATCH * GRP];
__device__ float g_rstd[BATCH * GRP];
__device__ float g_xn[MALL * CCH];
__device__ float g_q [MALL * CCH];
__device__ float g_k [MALL * CCH];
__device__ float g_vt[CCH * MALL];                       // V transposed: [256][16384]
__device__ float g_s [(long long)BATCH * NPIX * NPIX];   // 256 MB scores
__device__ float g_o [MALL * CCH];
__device__ float g_wT[4 * CCH * CCH];                    // wq^T, wk^T, wv^T, wp^T

// ---------------- GroupNorm statistics: one block per (b,g) ----------------
__global__ void gn_stats(const float* __restrict__ x) {
    int bg = blockIdx.x;            // 0..31
    int b = bg >> 3, g = bg & 7;
    const float* base = x + (long)b * NPIX * CCH + g * GSIZE;
    float s = 0.f, ss = 0.f;
    for (int i = threadIdx.x; i < NPIX * GSIZE; i += blockDim.x) {
        int p = i >> 5, c = i & 31;
        float v = base[(long)p * CCH + c];
        s += v; ss += v * v;
    }
    __shared__ float sh[16];
    #pragma unroll
    for (int o = 16; o > 0; o >>= 1) {
        s  += __shfl_xor_sync(0xffffffffu, s,  o);
        ss += __shfl_xor_sync(0xffffffffu, ss, o);
    }
    int w = threadIdx.x >> 5, l = threadIdx.x & 31;
    if (l == 0) { sh[w] = s; sh[8 + w] = ss; }
    __syncthreads();
    if (threadIdx.x == 0) {
        float S = 0.f, SS = 0.f;
        #pragma unroll
        for (int i = 0; i < 8; i++) { S += sh[i]; SS += sh[8 + i]; }
        const float invn = 1.0f / (NPIX * GSIZE);
        float mean = S * invn;
        float var  = SS * invn - mean * mean;
        g_mean[bg] = mean;
        g_rstd[bg] = rsqrtf(var + 1e-3f);
    }
}

// ---------------- GroupNorm apply (vectorized) ----------------
__global__ void gn_apply(const float* __restrict__ x,
                         const float* __restrict__ gamma,
                         const float* __restrict__ beta) {
    long i4 = (long)blockIdx.x * blockDim.x + threadIdx.x;   // float4 index
    float4 xv = ((const float4*)x)[i4];
    int c0 = (int)(i4 & 63) * 4;        // 64 float4 per channel row
    long row = i4 >> 6;                 // pixel index 0..16383
    int b = (int)(row >> 12);           // /4096
    int bg = b * 8 + (c0 >> 5);
    float m = g_mean[bg], r = g_rstd[bg];
    float4 o;
    o.x = (xv.x - m) * r * gamma[c0 + 0] + beta[c0 + 0];
    o.y = (xv.y - m) * r * gamma[c0 + 1] + beta[c0 + 1];
    o.z = (xv.z - m) * r * gamma[c0 + 2] + beta[c0 + 2];
    o.w = (xv.w - m) * r * gamma[c0 + 3] + beta[c0 + 3];
    ((float4*)g_xn)[i4] = o;
}

// ---------------- transpose the four 256x256 weight matrices ----------------
__global__ void transpose_w(const float* __restrict__ wq, const float* __restrict__ wk,
                            const float* __restrict__ wv, const float* __restrict__ wp) {
    __shared__ float t[32][33];
    int mat = blockIdx.z;
    const float* src = (mat == 0) ? wq : (mat == 1) ? wk : (mat == 2) ? wv : wp;
    int x0 = blockIdx.x * 32, y0 = blockIdx.y * 32;
    t[threadIdx.y][threadIdx.x] = src[(y0 + threadIdx.y) * CCH + x0 + threadIdx.x];
    __syncthreads();
    g_wT[mat * CCH * CCH + (x0 + threadIdx.y) * CCH + y0 + threadIdx.x] = t[threadIdx.x][threadIdx.y];
}

// ---------------- cp.async helpers ----------------
__device__ __forceinline__ void cp16(void* smem, const void* gmem) {
    unsigned s = (unsigned)__cvta_generic_to_shared(smem);
    asm volatile("cp.async.cg.shared.global [%0], [%1], 16;\n" :: "r"(s), "l"(gmem));
}
__device__ __forceinline__ void cp_commit() { asm volatile("cp.async.commit_group;\n"); }
__device__ __forceinline__ void cp_wait0() { asm volatile("cp.async.wait_group 0;\n"); }

__device__ __forceinline__ void mma_tf32(float* c, const unsigned* a, const unsigned* b) {
    asm volatile("mma.sync.aligned.m16n8k8.row.col.f32.tf32.tf32.f32 "
        "{%0,%1,%2,%3}, {%4,%5,%6,%7}, {%8,%9}, {%0,%1,%2,%3};"
        : "+f"(c[0]), "+f"(c[1]), "+f"(c[2]), "+f"(c[3])
        : "r"(a[0]), "r"(a[1]), "r"(a[2]), "r"(a[3]), "r"(b[0]), "r"(b[1]));
}

// ---------------- tf32 tensor-core GEMM:  C = alpha * A @ B^T (+biases)(+resid) ----------------
// A: [M,K] with leading-dim lda.  B: [N,K] with leading-dim ldb (dot over K).
// Grid: (N/128, M/128, batch).  K multiple of 16, M,N multiples of 128.
#define SMP 20   // smem row pitch (16 + 4 pad) — conflict-free for frag loads
template<bool BIASC, bool BIASR, bool RESID>
__global__ void __launch_bounds__(256, 2)
tcgemm(const float* __restrict__ A, int lda, long long sAz,
       const float* __restrict__ B, int ldb, long long sBz,
       float* __restrict__ C, int ldc, long long sCz,
       const float* __restrict__ biasc, const float* __restrict__ biasr,
       const float* __restrict__ resid, float alpha, int K)
{
    __shared__ float As[2][128][SMP];
    __shared__ float Bs[2][128][SMP];

    A += (long long)blockIdx.z * sAz;
    B += (long long)blockIdx.z * sBz;
    C += (long long)blockIdx.z * sCz;

    const int tid = threadIdx.x;
    const int m0 = blockIdx.y * 128, n0 = blockIdx.x * 128;

    // gmem->smem copy coords: 512 float4 per matrix per tile, 2 per thread
    const int arow = tid >> 2;            // 0..63
    const int ac   = (tid & 3) * 4;       // 0,4,8,12
    const float* Ag = A + (long long)(m0 + arow) * lda + ac;
    const float* Bg = B + (long long)(n0 + arow) * ldb + ac;

    const int w = tid >> 5, lane = tid & 31;
    const int wm = (w & 3) * 32, wn = (w >> 2) * 64;
    const int gid = lane >> 2, tg = lane & 3;

    float acc[2][8][4] = {};

    const int KT = K >> 4;

    // prologue: load tile 0 into buf 0
    {
        #pragma unroll
        for (int j = 0; j < 2; j++) {
            cp16(&As[0][arow + 64 * j][ac], Ag + (long long)64 * j * lda);
            cp16(&Bs[0][arow + 64 * j][ac], Bg + (long long)64 * j * ldb);
        }
        cp_commit();
    }

    for (int kt = 0; kt < KT; kt++) {
        cp_wait0();
        __syncthreads();
        if (kt + 1 < KT) {
            int buf = (kt + 1) & 1;
            long long ko = (long long)(kt + 1) * 16;
            #pragma unroll
            for (int j = 0; j < 2; j++) {
                cp16(&As[buf][arow + 64 * j][ac], Ag + (long long)64 * j * lda + ko);
                cp16(&Bs[buf][arow + 64 * j][ac], Bg + (long long)64 * j * ldb + ko);
            }
            cp_commit();
        }
        const int buf = kt & 1;
        const float (*as)[SMP] = As[buf];
        const float (*bs)[SMP] = Bs[buf];
        #pragma unroll
        for (int ks = 0; ks < 2; ks++) {
            const int k0 = ks * 8;
            unsigned a[2][4], b[8][2];
            #pragma unroll
            for (int mt = 0; mt < 2; mt++) {
                int r = wm + mt * 16 + gid;
                a[mt][0] = __float_as_uint(as[r][k0 + tg]);
                a[mt][1] = __float_as_uint(as[r + 8][k0 + tg]);
                a[mt][2] = __float_as_uint(as[r][k0 + tg + 4]);
                a[mt][3] = __float_as_uint(as[r + 8][k0 + tg + 4]);
            }
            #pragma unroll
            for (int nt = 0; nt < 8; nt++) {
                int c = wn + nt * 8 + gid;
                b[nt][0] = __float_as_uint(bs[c][k0 + tg]);
                b[nt][1] = __float_as_uint(bs[c][k0 + tg + 4]);
            }
            #pragma unroll
            for (int mt = 0; mt < 2; mt++)
                #pragma unroll
                for (int nt = 0; nt < 8; nt++)
                    mma_tf32(acc[mt][nt], a[mt], b[nt]);
        }
    }

    // epilogue
    #pragma unroll
    for (int mt = 0; mt < 2; mt++) {
        #pragma unroll
        for (int nt = 0; nt < 8; nt++) {
            int r0 = m0 + wm + mt * 16 + gid;
            int c0 = n0 + wn + nt * 8 + 2 * tg;
            #pragma unroll
            for (int h = 0; h < 2; h++) {
                int r = r0 + 8 * h;
                float v0 = acc[mt][nt][2 * h]     * alpha;
                float v1 = acc[mt][nt][2 * h + 1] * alpha;
                if (BIASC) { v0 += biasc[c0]; v1 += biasc[c0 + 1]; }
                if (BIASR) { float rb = biasr[r]; v0 += rb; v1 += rb; }
                long long off = (long long)r * ldc + c0;
                if (RESID) { v0 += resid[off]; v1 += resid[off + 1]; }
                *(float2*)&C[off] = make_float2(v0, v1);
            }
        }
    }
}

// ---------------- Row softmax over width 4096, one block per row ----------------
__global__ void softmax4096(float* __restrict__ S) {
    float4* row = (float4*)(S + (long long)blockIdx.x * 4096);
    int tid = threadIdx.x;   // 256
    float4 v[4];
    float mx = -1e30f;
    #pragma unroll
    for (int i = 0; i < 4; i++) {
        v[i] = row[tid + i * 256];
        mx = fmaxf(mx, fmaxf(fmaxf(v[i].x, v[i].y), fmaxf(v[i].z, v[i].w)));
    }
    __shared__ float sh[8];
    #pragma unroll
    for (int o = 16; o > 0; o >>= 1) mx = fmaxf(mx, __shfl_xor_sync(0xffffffffu, mx, o));
    if ((tid & 31) == 0) sh[tid >> 5] = mx;
    __syncthreads();
    mx = sh[0];
    #pragma unroll
    for (int i = 1; i < 8; i++) mx = fmaxf(mx, sh[i]);

    float sum = 0.f;
    #pragma unroll
    for (int i = 0; i < 4; i++) {
        v[i].x = __expf(v[i].x - mx); v[i].y = __expf(v[i].y - mx);
        v[i].z = __expf(v[i].z - mx); v[i].w = __expf(v[i].w - mx);
        sum += v[i].x + v[i].y + v[i].z + v[i].w;
    }
    __syncthreads();   // sh reuse
    #pragma unroll
    for (int o = 16; o > 0; o >>= 1) sum += __shfl_xor_sync(0xffffffffu, sum, o);
    if ((tid & 31) == 0) sh[tid >> 5] = sum;
    __syncthreads();
    float tot = 0.f;
    #pragma unroll
    for (int i = 0; i < 8; i++) tot += sh[i];
    float inv = 1.0f / tot;
    #pragma unroll
    for (int i = 0; i < 4; i++) {
        v[i].x *= inv; v[i].y *= inv; v[i].z *= inv; v[i].w *= inv;
        row[tid + i * 256] = v[i];
    }
}

// ---------------- launch ----------------
extern "C" void kernel_launch(void* const* d_in, const int* in_sizes, int n_in,
                              void* d_out, int out_size) {
    const float* x     = (const float*)d_in[0];
    const float* gamma = (const float*)d_in[1];
    const float* beta  = (const float*)d_in[2];
    const float* wq    = (const float*)d_in[3];
    const float* bq    = (const float*)d_in[4];
    const float* wk    = (const float*)d_in[5];
    const float* bk    = (const float*)d_in[6];
    const float* wv    = (const float*)d_in[7];
    const float* bv    = (const float*)d_in[8];
    const float* wp    = (const float*)d_in[9];
    const float* bp    = (const float*)d_in[10];
    float* out = (float*)d_out;

    float *xn, *q, *k, *vt, *s, *o, *wT;
    cudaGetSymbolAddress((void**)&xn, g_xn);
    cudaGetSymbolAddress((void**)&q,  g_q);
    cudaGetSymbolAddress((void**)&k,  g_k);
    cudaGetSymbolAddress((void**)&vt, g_vt);
    cudaGetSymbolAddress((void**)&s,  g_s);
    cudaGetSymbolAddress((void**)&o,  g_o);
    cudaGetSymbolAddress((void**)&wT, g_wT);

    // 1. GroupNorm
    gn_stats<<<BATCH * GRP, 256>>>(x);
    gn_apply<<<(MALL * CCH / 4) / 256, 256>>>(x, gamma, beta);

    // 2. transpose weights (wq^T, wk^T, wv^T, wp^T)
    transpose_w<<<dim3(8, 8, 4), dim3(32, 32)>>>(wq, wk, wv, wp);

    // 3. Q = xn @ wq + bq     (A=xn[16384,256], B=wqT[256,256])
    tcgemm<true, false, false><<<dim3(2, 128, 1), 256>>>(
        xn, CCH, 0, wT + 0 * CCH * CCH, CCH, 0, q, CCH, 0,
        bq, nullptr, nullptr, 1.0f, CCH);
    // 4. K = xn @ wk + bk
    tcgemm<true, false, false><<<dim3(2, 128, 1), 256>>>(
        xn, CCH, 0, wT + 1 * CCH * CCH, CCH, 0, k, CCH, 0,
        bk, nullptr, nullptr, 1.0f, CCH);
    // 5. VT[c, m] = sum_k wvT[c,k] * xn[m,k] + bv[c]   (V produced transposed)
    tcgemm<false, true, false><<<dim3(MALL / 128, CCH / 128, 1), 256>>>(
        wT + 2 * CCH * CCH, CCH, 0, xn, CCH, 0, vt, MALL, 0,
        nullptr, bv, nullptr, 1.0f, CCH);

    // 6. scores = Q @ K^T / 16  (per batch)
    tcgemm<false, false, false><<<dim3(NPIX / 128, NPIX / 128, BATCH), 256>>>(
        q, CCH, (long long)NPIX * CCH, k, CCH, (long long)NPIX * CCH,
        s, NPIX, (long long)NPIX * NPIX,
        nullptr, nullptr, nullptr, 0.0625f, CCH);

    // 7. softmax rows
    softmax4096<<<BATCH * NPIX, 256>>>(s);

    // 8. O = attn @ V = attn @ VT^T  (per batch; B = VT sub-block of columns)
    tcgemm<false, false, false><<<dim3(CCH / 128, NPIX / 128, BATCH), 256>>>(
        s, NPIX, (long long)NPIX * NPIX, vt, MALL, (long long)NPIX,
        o, CCH, (long long)NPIX * CCH,
        nullptr, nullptr, nullptr, 1.0f, NPIX);

    // 9. y = x + O @ wp + bp
    tcgemm<true, false, true><<<dim3(2, 128, 1), 256>>>(
        o, CCH, 0, wT + 3 * CCH * CCH, CCH, 0, out, CCH, 0,
        bp, nullptr, x, 1.0f, CCH);
}

// round 5
// speedup vs baseline: 4.8329x; 1.0718x over previous
#include <cuda_runtime.h>
#include <cstdint>

// Problem constants (fixed shapes from reference)
#define BATCH   4
#define NPIX    4096          // H*W = 64*64
#define CCH     256
#define GRP     8
#define GSIZE   32            // CCH / GRP
#define MALL    16384         // BATCH * NPIX

// -------- scratch (static device globals; no allocation) --------
__device__ float g_mean[BATCH * GRP];
__device__ float g_rstd[BATCH * GRP];
__device__ float g_xn[MALL * CCH];
__device__ float g_q [MALL * CCH];
__device__ float g_k [MALL * CCH];
__device__ float g_vt[CCH * MALL];                       // V transposed: [256][16384]
__device__ float g_s [(long long)BATCH * NPIX * NPIX];   // exp'd scores
__device__ float g_o [MALL * CCH];
__device__ float g_wT[4 * CCH * CCH];                    // wq^T, wk^T, wv^T, wp^T
__device__ float g_Lp[64 * MALL];                        // row-sum partials [64][16384]
__device__ float g_inv[MALL];                            // 1 / rowsum

// ---------------- GroupNorm statistics: one block per (b,g) ----------------
__global__ void gn_stats(const float* __restrict__ x) {
    int bg = blockIdx.x;            // 0..31
    int b = bg >> 3, g = bg & 7;
    const float* base = x + (long)b * NPIX * CCH + g * GSIZE;
    float s = 0.f, ss = 0.f;
    for (int i = threadIdx.x; i < NPIX * GSIZE; i += blockDim.x) {
        int p = i >> 5, c = i & 31;
        float v = base[(long)p * CCH + c];
        s += v; ss += v * v;
    }
    __shared__ float sh[16];
    #pragma unroll
    for (int o = 16; o > 0; o >>= 1) {
        s  += __shfl_xor_sync(0xffffffffu, s,  o);
        ss += __shfl_xor_sync(0xffffffffu, ss, o);
    }
    int w = threadIdx.x >> 5, l = threadIdx.x & 31;
    if (l == 0) { sh[w] = s; sh[8 + w] = ss; }
    __syncthreads();
    if (threadIdx.x == 0) {
        float S = 0.f, SS = 0.f;
        #pragma unroll
        for (int i = 0; i < 8; i++) { S += sh[i]; SS += sh[8 + i]; }
        const float invn = 1.0f / (NPIX * GSIZE);
        float mean = S * invn;
        float var  = SS * invn - mean * mean;
        g_mean[bg] = mean;
        g_rstd[bg] = rsqrtf(var + 1e-3f);
    }
}

// ---------------- GroupNorm apply (vectorized) ----------------
__global__ void gn_apply(const float* __restrict__ x,
                         const float* __restrict__ gamma,
                         const float* __restrict__ beta) {
    long i4 = (long)blockIdx.x * blockDim.x + threadIdx.x;   // float4 index
    float4 xv = ((const float4*)x)[i4];
    int c0 = (int)(i4 & 63) * 4;        // 64 float4 per channel row
    long row = i4 >> 6;                 // pixel index 0..16383
    int b = (int)(row >> 12);           // /4096
    int bg = b * 8 + (c0 >> 5);
    float m = g_mean[bg], r = g_rstd[bg];
    float4 o;
    o.x = (xv.x - m) * r * gamma[c0 + 0] + beta[c0 + 0];
    o.y = (xv.y - m) * r * gamma[c0 + 1] + beta[c0 + 1];
    o.z = (xv.z - m) * r * gamma[c0 + 2] + beta[c0 + 2];
    o.w = (xv.w - m) * r * gamma[c0 + 3] + beta[c0 + 3];
    ((float4*)g_xn)[i4] = o;
}

// ---------------- transpose the four 256x256 weight matrices ----------------
__global__ void transpose_w(const float* __restrict__ wq, const float* __restrict__ wk,
                            const float* __restrict__ wv, const float* __restrict__ wp) {
    __shared__ float t[32][33];
    int mat = blockIdx.z;
    const float* src = (mat == 0) ? wq : (mat == 1) ? wk : (mat == 2) ? wv : wp;
    int x0 = blockIdx.x * 32, y0 = blockIdx.y * 32;
    t[threadIdx.y][threadIdx.x] = src[(y0 + threadIdx.y) * CCH + x0 + threadIdx.x];
    __syncthreads();
    g_wT[mat * CCH * CCH + (x0 + threadIdx.y) * CCH + y0 + threadIdx.x] = t[threadIdx.x][threadIdx.y];
}

// ---------------- cp.async helpers ----------------
__device__ __forceinline__ void cp16g(void* smem, const void* gmem) {
    unsigned s = (unsigned)__cvta_generic_to_shared(smem);
    asm volatile("cp.async.cg.shared.global [%0], [%1], 16;\n" :: "r"(s), "l"(gmem));
}
__device__ __forceinline__ void cp_commit() { asm volatile("cp.async.commit_group;\n"); }
__device__ __forceinline__ void cp_wait0() { asm volatile("cp.async.wait_group 0;\n"); }
__device__ __forceinline__ void cp_wait1() { asm volatile("cp.async.wait_group 1;\n"); }

__device__ __forceinline__ void mma_tf32(float* c, const unsigned* a, const unsigned* b) {
    asm volatile("mma.sync.aligned.m16n8k8.row.col.f32.tf32.tf32.f32 "
        "{%0,%1,%2,%3}, {%4,%5,%6,%7}, {%8,%9}, {%0,%1,%2,%3};"
        : "+f"(c[0]), "+f"(c[1]), "+f"(c[2]), "+f"(c[3])
        : "r"(a[0]), "r"(a[1]), "r"(a[2]), "r"(a[3]), "r"(b[0]), "r"(b[1]));
}

// ================= big tf32 GEMM: C = A @ B^T, CTA tile 128x256 =================
// A: [M,K] lda, B: [N,K] ldb (dot over K). Batched via blockIdx.z.
// EPI 1: C = exp(alpha*acc), write per-(row, warp-col) partial sums to Lp.
// EPI 2: C = acc * inv[row].
// Warp tile 64x64: warps 2(m) x 4(n). 3-stage cp.async pipeline, K-slab 16.
#define BP 20                     // smem row pitch in floats
#define STAGE_F (384 * BP)        // floats per stage
template<int EPI>
__global__ void __launch_bounds__(256, 1)
tcbig(const float* __restrict__ A, int lda, long long sAz,
      const float* __restrict__ B, int ldb, long long sBz,
      float* __restrict__ C, int ldc, long long sCz,
      float* __restrict__ Lp, const float* __restrict__ inv,
      float alpha, int K)
{
    extern __shared__ float sm[];    // [3][384][BP]

    A += (long long)blockIdx.z * sAz;
    B += (long long)blockIdx.z * sBz;
    C += (long long)blockIdx.z * sCz;

    const int tid = threadIdx.x;
    const int w = tid >> 5, lane = tid & 31;
    const int gid = lane >> 2, tg = lane & 3;
    const int wm = (w >> 2) * 64;        // 0 or 64
    const int wn = (w & 3) * 64;         // 0,64,128,192
    const long long m0 = (long long)blockIdx.y * 128;
    const long long n0 = (long long)blockIdx.x * 256;

    // per-thread loader addresses (6 chunks of 16B per stage), hoisted
    const float* gsrc[6];
    float* sdst[6];
    #pragma unroll
    for (int j = 0; j < 6; j++) {
        int idx = tid + j * 256;         // 0..1535
        int r = idx >> 2, c16 = idx & 3; // row 0..383, 16B chunk 0..3
        if (r < 128) gsrc[j] = A + (m0 + r) * lda + c16 * 4;
        else         gsrc[j] = B + (n0 + r - 128) * (long long)ldb + c16 * 4;
        sdst[j] = sm + r * BP + c16 * 4;
    }

    float acc[4][8][4] = {};
    const int KC = K >> 4;

    auto load_stage = [&](int kc, int st) {
        const float* ko = (const float*)0 + kc * 16;  // offset trick avoided; use direct
        #pragma unroll
        for (int j = 0; j < 6; j++)
            cp16g(sdst[j] + st * STAGE_F, gsrc[j] + kc * 16);
        cp_commit();
        (void)ko;
    };

    load_stage(0, 0);
    load_stage(1, 1);

    for (int kc = 0; kc < KC; kc++) {
        if (kc + 1 < KC) cp_wait1(); else cp_wait0();
        __syncthreads();
        if (kc + 2 < KC) load_stage(kc + 2, (kc + 2) % 3);

        const float* st = sm + (kc % 3) * STAGE_F;
        const float* as = st;                 // rows 0..127
        const float* bs = st + 128 * BP;      // rows 0..255
        #pragma unroll
        for (int ks = 0; ks < 2; ks++) {
            const int k0 = ks * 8;
            unsigned a[4][4], b[8][2];
            #pragma unroll
            for (int mt = 0; mt < 4; mt++) {
                int r = wm + mt * 16 + gid;
                a[mt][0] = __float_as_uint(as[r * BP + k0 + tg]);
                a[mt][1] = __float_as_uint(as[(r + 8) * BP + k0 + tg]);
                a[mt][2] = __float_as_uint(as[r * BP + k0 + tg + 4]);
                a[mt][3] = __float_as_uint(as[(r + 8) * BP + k0 + tg + 4]);
            }
            #pragma unroll
            for (int nt = 0; nt < 8; nt++) {
                int c = wn + nt * 8 + gid;
                b[nt][0] = __float_as_uint(bs[c * BP + k0 + tg]);
                b[nt][1] = __float_as_uint(bs[c * BP + k0 + tg + 4]);
            }
            #pragma unroll
            for (int mt = 0; mt < 4; mt++)
                #pragma unroll
                for (int nt = 0; nt < 8; nt++)
                    mma_tf32(acc[mt][nt], a[mt], b[nt]);
        }
    }

    // ---------------- epilogue ----------------
    #pragma unroll
    for (int mt = 0; mt < 4; mt++) {
        #pragma unroll
        for (int h = 0; h < 2; h++) {
            int rloc = wm + mt * 16 + gid + 8 * h;       // 0..127
            long long row = m0 + rloc;
            float* Crow = C + row * ldc + n0 + wn + 2 * tg;
            if (EPI == 1) {
                float rowsum = 0.f;
                #pragma unroll
                for (int nt = 0; nt < 8; nt++) {
                    float v0 = __expf(acc[mt][nt][2 * h]     * alpha);
                    float v1 = __expf(acc[mt][nt][2 * h + 1] * alpha);
                    rowsum += v0 + v1;
                    *(float2*)&Crow[nt * 8] = make_float2(v0, v1);
                }
                rowsum += __shfl_xor_sync(0xffffffffu, rowsum, 1);
                rowsum += __shfl_xor_sync(0xffffffffu, rowsum, 2);
                if (tg == 0)
                    Lp[(blockIdx.x * 4 + (w & 3)) * (long long)MALL
                       + blockIdx.z * (long long)NPIX + row] = rowsum;
            } else {
                float rs = inv[blockIdx.z * (long long)NPIX + row];
                #pragma unroll
                for (int nt = 0; nt < 8; nt++) {
                    float v0 = acc[mt][nt][2 * h]     * rs;
                    float v1 = acc[mt][nt][2 * h + 1] * rs;
                    *(float2*)&Crow[nt * 8] = make_float2(v0, v1);
                }
            }
        }
    }
}

// ---------------- rowsum inverse: inv[i] = 1 / sum_j Lp[j][i] ----------------
__global__ void rowsum_inv(const float* __restrict__ Lp, float* __restrict__ inv) {
    int i = blockIdx.x * 256 + threadIdx.x;
    float s = 0.f;
    #pragma unroll
    for (int j = 0; j < 64; j++) s += Lp[j * MALL + i];
    inv[i] = 1.0f / s;
}

// ---------------- legacy tf32 tensor-core GEMM (QKV / proj, proven) ----------------
#define SMP 20
template<bool BIASC, bool BIASR, bool RESID>
__global__ void __launch_bounds__(256, 2)
tcgemm(const float* __restrict__ A, int lda, long long sAz,
       const float* __restrict__ B, int ldb, long long sBz,
       float* __restrict__ C, int ldc, long long sCz,
       const float* __restrict__ biasc, const float* __restrict__ biasr,
       const float* __restrict__ resid, float alpha, int K)
{
    __shared__ float As[2][128][SMP];
    __shared__ float Bs[2][128][SMP];

    A += (long long)blockIdx.z * sAz;
    B += (long long)blockIdx.z * sBz;
    C += (long long)blockIdx.z * sCz;

    const int tid = threadIdx.x;
    const int m0 = blockIdx.y * 128, n0 = blockIdx.x * 128;

    const int arow = tid >> 2;
    const int ac   = (tid & 3) * 4;
    const float* Ag = A + (long long)(m0 + arow) * lda + ac;
    const float* Bg = B + (long long)(n0 + arow) * ldb + ac;

    const int w = tid >> 5, lane = tid & 31;
    const int wm = (w & 3) * 32, wn = (w >> 2) * 64;
    const int gid = lane >> 2, tg = lane & 3;

    float acc[2][8][4] = {};
    const int KT = K >> 4;

    {
        #pragma unroll
        for (int j = 0; j < 2; j++) {
            cp16g(&As[0][arow + 64 * j][ac], Ag + (long long)64 * j * lda);
            cp16g(&Bs[0][arow + 64 * j][ac], Bg + (long long)64 * j * ldb);
        }
        cp_commit();
    }

    for (int kt = 0; kt < KT; kt++) {
        cp_wait0();
        __syncthreads();
        if (kt + 1 < KT) {
            int buf = (kt + 1) & 1;
            long long ko = (long long)(kt + 1) * 16;
            #pragma unroll
            for (int j = 0; j < 2; j++) {
                cp16g(&As[buf][arow + 64 * j][ac], Ag + (long long)64 * j * lda + ko);
                cp16g(&Bs[buf][arow + 64 * j][ac], Bg + (long long)64 * j * ldb + ko);
            }
            cp_commit();
        }
        const int buf = kt & 1;
        const float (*as)[SMP] = As[buf];
        const float (*bs)[SMP] = Bs[buf];
        #pragma unroll
        for (int ks = 0; ks < 2; ks++) {
            const int k0 = ks * 8;
            unsigned a[2][4], b[8][2];
            #pragma unroll
            for (int mt = 0; mt < 2; mt++) {
                int r = wm + mt * 16 + gid;
                a[mt][0] = __float_as_uint(as[r][k0 + tg]);
                a[mt][1] = __float_as_uint(as[r + 8][k0 + tg]);
                a[mt][2] = __float_as_uint(as[r][k0 + tg + 4]);
                a[mt][3] = __float_as_uint(as[r + 8][k0 + tg + 4]);
            }
            #pragma unroll
            for (int nt = 0; nt < 8; nt++) {
                int c = wn + nt * 8 + gid;
                b[nt][0] = __float_as_uint(bs[c][k0 + tg]);
                b[nt][1] = __float_as_uint(bs[c][k0 + tg + 4]);
            }
            #pragma unroll
            for (int mt = 0; mt < 2; mt++)
                #pragma unroll
                for (int nt = 0; nt < 8; nt++)
                    mma_tf32(acc[mt][nt], a[mt], b[nt]);
        }
        __syncthreads();
    }

    #pragma unroll
    for (int mt = 0; mt < 2; mt++) {
        #pragma unroll
        for (int nt = 0; nt < 8; nt++) {
            int r0 = m0 + wm + mt * 16 + gid;
            int c0 = n0 + wn + nt * 8 + 2 * tg;
            #pragma unroll
            for (int h = 0; h < 2; h++) {
                int r = r0 + 8 * h;
                float v0 = acc[mt][nt][2 * h]     * alpha;
                float v1 = acc[mt][nt][2 * h + 1] * alpha;
                if (BIASC) { v0 += biasc[c0]; v1 += biasc[c0 + 1]; }
                if (BIASR) { float rb = biasr[r]; v0 += rb; v1 += rb; }
                long long off = (long long)r * ldc + c0;
                if (RESID) { v0 += resid[off]; v1 += resid[off + 1]; }
                *(float2*)&C[off] = make_float2(v0, v1);
            }
        }
    }
}

// ---------------- launch ----------------
extern "C" void kernel_launch(void* const* d_in, const int* in_sizes, int n_in,
                              void* d_out, int out_size) {
    const float* x     = (const float*)d_in[0];
    const float* gamma = (const float*)d_in[1];
    const float* beta  = (const float*)d_in[2];
    const float* wq    = (const float*)d_in[3];
    const float* bq    = (const float*)d_in[4];
    const float* wk    = (const float*)d_in[5];
    const float* bk    = (const float*)d_in[6];
    const float* wv    = (const float*)d_in[7];
    const float* bv    = (const float*)d_in[8];
    const float* wp    = (const float*)d_in[9];
    const float* bp    = (const float*)d_in[10];
    float* out = (float*)d_out;

    float *xn, *q, *k, *vt, *s, *o, *wT, *Lp, *inv;
    cudaGetSymbolAddress((void**)&xn, g_xn);
    cudaGetSymbolAddress((void**)&q,  g_q);
    cudaGetSymbolAddress((void**)&k,  g_k);
    cudaGetSymbolAddress((void**)&vt, g_vt);
    cudaGetSymbolAddress((void**)&s,  g_s);
    cudaGetSymbolAddress((void**)&o,  g_o);
    cudaGetSymbolAddress((void**)&wT, g_wT);
    cudaGetSymbolAddress((void**)&Lp, g_Lp);
    cudaGetSymbolAddress((void**)&inv, g_inv);

    const int SMB = 3 * STAGE_F * 4;      // 92,160 B dynamic smem
    cudaFuncSetAttribute(tcbig<1>, cudaFuncAttributeMaxDynamicSharedMemorySize, SMB);
    cudaFuncSetAttribute(tcbig<2>, cudaFuncAttributeMaxDynamicSharedMemorySize, SMB);

    // 1. GroupNorm
    gn_stats<<<BATCH * GRP, 256>>>(x);
    gn_apply<<<(MALL * CCH / 4) / 256, 256>>>(x, gamma, beta);

    // 2. transpose weights
    transpose_w<<<dim3(8, 8, 4), dim3(32, 32)>>>(wq, wk, wv, wp);

    // 3. Q / K / VT projections
    tcgemm<true, false, false><<<dim3(2, 128, 1), 256>>>(
        xn, CCH, 0, wT + 0 * CCH * CCH, CCH, 0, q, CCH, 0,
        bq, nullptr, nullptr, 1.0f, CCH);
    tcgemm<true, false, false><<<dim3(2, 128, 1), 256>>>(
        xn, CCH, 0, wT + 1 * CCH * CCH, CCH, 0, k, CCH, 0,
        bk, nullptr, nullptr, 1.0f, CCH);
    tcgemm<false, true, false><<<dim3(MALL / 128, CCH / 128, 1), 256>>>(
        wT + 2 * CCH * CCH, CCH, 0, xn, CCH, 0, vt, MALL, 0,
        nullptr, bv, nullptr, 1.0f, CCH);

    // 4. S = exp(Q @ K^T / 16), plus row-sum partials
    tcbig<1><<<dim3(NPIX / 256, NPIX / 128, BATCH), 256, SMB>>>(
        q, CCH, (long long)NPIX * CCH,
        k, CCH, (long long)NPIX * CCH,
        s, NPIX, (long long)NPIX * NPIX,
        Lp, nullptr, 0.0625f, CCH);

    // 5. inv[row] = 1 / rowsum
    rowsum_inv<<<MALL / 256, 256>>>(Lp, inv);

    // 6. O = (S @ V) * inv   (K = 4096)
    tcbig<2><<<dim3(CCH / 256, NPIX / 128, BATCH), 256, SMB>>>(
        s, NPIX, (long long)NPIX * NPIX,
        vt, MALL, (long long)NPIX,
        o, CCH, (long long)NPIX * CCH,
        nullptr, inv, 1.0f, NPIX);

    // 7. y = x + O @ wp + bp
    tcgemm<true, false, true><<<dim3(2, 128, 1), 256>>>(
        o, CCH, 0, wT + 3 * CCH * CCH, CCH, 0, out, CCH, 0,
        bp, nullptr, x, 1.0f, CCH);
}

// round 6
// speedup vs baseline: 7.0272x; 1.4541x over previous
#include <cuda_runtime.h>
#include <cuda_fp16.h>
#include <cstdint>

// Problem constants (fixed shapes from reference)
#define BATCH   4
#define NPIX    4096          // H*W = 64*64
#define CCH     256
#define GRP     8
#define GSIZE   32            // CCH / GRP
#define MALL    16384         // BATCH * NPIX

// -------- scratch (static device globals; no allocation) --------
__device__ float g_mean[BATCH * GRP];
__device__ float g_rstd[BATCH * GRP];
__device__ float g_xn[MALL * CCH];
__device__ __half g_qh[MALL * CCH];
__device__ __half g_kh[MALL * CCH];
__device__ __half g_vth[CCH * MALL];                      // V transposed (fp16): [256][16384]
__device__ __half g_sh[(long long)BATCH * NPIX * NPIX];   // exp'd scores, fp16 (128 MB)
__device__ float g_o [MALL * CCH];
__device__ float g_wT[4 * CCH * CCH];                     // wq^T, wk^T, wv^T, wp^T
__device__ float g_Lp[64 * MALL];                         // row-sum partials [64][16384]
__device__ float g_inv[MALL];                             // 1 / rowsum

// ---------------- GroupNorm statistics: one block per (b,g) ----------------
__global__ void gn_stats(const float* __restrict__ x) {
    int bg = blockIdx.x;            // 0..31
    int b = bg >> 3, g = bg & 7;
    const float* base = x + (long)b * NPIX * CCH + g * GSIZE;
    float s = 0.f, ss = 0.f;
    for (int i = threadIdx.x; i < NPIX * GSIZE; i += blockDim.x) {
        int p = i >> 5, c = i & 31;
        float v = base[(long)p * CCH + c];
        s += v; ss += v * v;
    }
    __shared__ float sh[16];
    #pragma unroll
    for (int o = 16; o > 0; o >>= 1) {
        s  += __shfl_xor_sync(0xffffffffu, s,  o);
        ss += __shfl_xor_sync(0xffffffffu, ss, o);
    }
    int w = threadIdx.x >> 5, l = threadIdx.x & 31;
    if (l == 0) { sh[w] = s; sh[8 + w] = ss; }
    __syncthreads();
    if (threadIdx.x == 0) {
        float S = 0.f, SS = 0.f;
        #pragma unroll
        for (int i = 0; i < 8; i++) { S += sh[i]; SS += sh[8 + i]; }
        const float invn = 1.0f / (NPIX * GSIZE);
        float mean = S * invn;
        float var  = SS * invn - mean * mean;
        g_mean[bg] = mean;
        g_rstd[bg] = rsqrtf(var + 1e-3f);
    }
}

// ---------------- GroupNorm apply (vectorized) ----------------
__global__ void gn_apply(const float* __restrict__ x,
                         const float* __restrict__ gamma,
                         const float* __restrict__ beta) {
    long i4 = (long)blockIdx.x * blockDim.x + threadIdx.x;   // float4 index
    float4 xv = ((const float4*)x)[i4];
    int c0 = (int)(i4 & 63) * 4;        // 64 float4 per channel row
    long row = i4 >> 6;                 // pixel index 0..16383
    int b = (int)(row >> 12);           // /4096
    int bg = b * 8 + (c0 >> 5);
    float m = g_mean[bg], r = g_rstd[bg];
    float4 o;
    o.x = (xv.x - m) * r * gamma[c0 + 0] + beta[c0 + 0];
    o.y = (xv.y - m) * r * gamma[c0 + 1] + beta[c0 + 1];
    o.z = (xv.z - m) * r * gamma[c0 + 2] + beta[c0 + 2];
    o.w = (xv.w - m) * r * gamma[c0 + 3] + beta[c0 + 3];
    ((float4*)g_xn)[i4] = o;
}

// ---------------- transpose the four 256x256 weight matrices ----------------
__global__ void transpose_w(const float* __restrict__ wq, const float* __restrict__ wk,
                            const float* __restrict__ wv, const float* __restrict__ wp) {
    __shared__ float t[32][33];
    int mat = blockIdx.z;
    const float* src = (mat == 0) ? wq : (mat == 1) ? wk : (mat == 2) ? wv : wp;
    int x0 = blockIdx.x * 32, y0 = blockIdx.y * 32;
    t[threadIdx.y][threadIdx.x] = src[(y0 + threadIdx.y) * CCH + x0 + threadIdx.x];
    __syncthreads();
    g_wT[mat * CCH * CCH + (x0 + threadIdx.y) * CCH + y0 + threadIdx.x] = t[threadIdx.x][threadIdx.y];
}

// ---------------- cp.async helpers ----------------
__device__ __forceinline__ void cp16g(void* smem, const void* gmem) {
    unsigned s = (unsigned)__cvta_generic_to_shared(smem);
    asm volatile("cp.async.cg.shared.global [%0], [%1], 16;\n" :: "r"(s), "l"(gmem));
}
__device__ __forceinline__ void cp_commit() { asm volatile("cp.async.commit_group;\n"); }
__device__ __forceinline__ void cp_wait0() { asm volatile("cp.async.wait_group 0;\n"); }

__device__ __forceinline__ void mma_tf32(float* c, const unsigned* a, const unsigned* b) {
    asm volatile("mma.sync.aligned.m16n8k8.row.col.f32.tf32.tf32.f32 "
        "{%0,%1,%2,%3}, {%4,%5,%6,%7}, {%8,%9}, {%0,%1,%2,%3};"
        : "+f"(c[0]), "+f"(c[1]), "+f"(c[2]), "+f"(c[3])
        : "r"(a[0]), "r"(a[1]), "r"(a[2]), "r"(a[3]), "r"(b[0]), "r"(b[1]));
}
__device__ __forceinline__ void mma_f16(float* c, const unsigned* a, const unsigned* b) {
    asm volatile("mma.sync.aligned.m16n8k16.row.col.f32.f16.f16.f32 "
        "{%0,%1,%2,%3}, {%4,%5,%6,%7}, {%8,%9}, {%0,%1,%2,%3};"
        : "+f"(c[0]), "+f"(c[1]), "+f"(c[2]), "+f"(c[3])
        : "r"(a[0]), "r"(a[1]), "r"(a[2]), "r"(a[3]), "r"(b[0]), "r"(b[1]));
}

// ================= fp16 big GEMM: C = f(A @ B^T), CTA 128x128, warp 32x64 =================
// A: [M,K] halves lda, B: [N,K] halves ldb (dot over K). Batched via blockIdx.z.
// EPI 1: C(half) = exp(alpha*acc); per-(row, col-warp) partial sums -> Lp[64][MALL].
// EPI 2: C(float) = acc * inv[row].
#define HP 40                      // smem pitch in halves (32 data + 8 pad) -> 80 B rows
template<int EPI>
__global__ void __launch_bounds__(256, 2)
hgemm(const __half* __restrict__ A, int lda, long long sAz,
      const __half* __restrict__ B, int ldb, long long sBz,
      void* __restrict__ Cv, int ldc, long long sCz,
      float* __restrict__ Lp, const float* __restrict__ inv,
      float alpha, int K)
{
    __shared__ __align__(16) __half As[2][128 * HP];
    __shared__ __align__(16) __half Bs[2][128 * HP];

    A += (long long)blockIdx.z * sAz;
    B += (long long)blockIdx.z * sBz;

    const int tid = threadIdx.x;
    const int w = tid >> 5, lane = tid & 31;
    const int gid = lane >> 2, tig = lane & 3;
    const int wm = (w & 3) * 32;        // 4 m-warps
    const int wn = (w >> 2) * 64;       // 2 n-warps
    const int wg = w >> 2;
    const long long m0 = (long long)blockIdx.y * 128;
    const long long n0 = (long long)blockIdx.x * 128;

    // loader coords: 512 16B-chunks per matrix per stage, 2 per thread each
    const int lr = tid >> 1;            // row 0..127
    const int lc = (tid & 1) * 16;      // half-offset 0 or 16 (16B chunks 0,1 then 2,3)
    const __half* Ag = A + (m0 + lr) * lda + lc;
    const __half* Bg = B + (n0 + lr) * (long long)ldb + lc;
    __half* Asd = &As[0][lr * HP + lc];
    __half* Bsd = &Bs[0][lr * HP + lc];

    float acc[2][8][4] = {};
    const int KT = K >> 5;              // slabs of 32 halves

    // prologue: stage 0
    cp16g(Asd, Ag);            cp16g(Asd + 8, Ag + 8);
    cp16g(Bsd, Bg);            cp16g(Bsd + 8, Bg + 8);
    cp_commit();

    for (int kt = 0; kt < KT; kt++) {
        cp_wait0();
        __syncthreads();
        if (kt + 1 < KT) {
            int buf = (kt + 1) & 1;
            long long ko = (long long)(kt + 1) * 32;
            __half* ad = Asd + buf * 128 * HP;
            __half* bd = Bsd + buf * 128 * HP;
            cp16g(ad, Ag + ko);        cp16g(ad + 8, Ag + ko + 8);
            cp16g(bd, Bg + ko);        cp16g(bd + 8, Bg + ko + 8);
            cp_commit();
        }
        const __half* as = As[kt & 1];
        const __half* bs = Bs[kt & 1];
        #pragma unroll
        for (int kk = 0; kk < 32; kk += 16) {
            unsigned a[2][4], b[8][2];
            #pragma unroll
            for (int mt = 0; mt < 2; mt++) {
                int r = wm + mt * 16 + gid;
                a[mt][0] = *(const unsigned*)&as[r * HP + kk + 2 * tig];
                a[mt][1] = *(const unsigned*)&as[(r + 8) * HP + kk + 2 * tig];
                a[mt][2] = *(const unsigned*)&as[r * HP + kk + 2 * tig + 8];
                a[mt][3] = *(const unsigned*)&as[(r + 8) * HP + kk + 2 * tig + 8];
            }
            #pragma unroll
            for (int nt = 0; nt < 8; nt++) {
                int c = wn + nt * 8 + gid;
                b[nt][0] = *(const unsigned*)&bs[c * HP + kk + 2 * tig];
                b[nt][1] = *(const unsigned*)&bs[c * HP + kk + 2 * tig + 8];
            }
            #pragma unroll
            for (int mt = 0; mt < 2; mt++)
                #pragma unroll
                for (int nt = 0; nt < 8; nt++)
                    mma_f16(acc[mt][nt], a[mt], b[nt]);
        }
        __syncthreads();
    }

    // ---------------- epilogue ----------------
    #pragma unroll
    for (int mt = 0; mt < 2; mt++) {
        #pragma unroll
        for (int h = 0; h < 2; h++) {
            long long row = m0 + wm + mt * 16 + gid + 8 * h;
            long long cbase = row * ldc + n0 + wn + 2 * tig;
            if (EPI == 1) {
                __half* C = (__half*)Cv + (long long)blockIdx.z * sCz;
                float rowsum = 0.f;
                #pragma unroll
                for (int nt = 0; nt < 8; nt++) {
                    float v0 = __expf(acc[mt][nt][2 * h]     * alpha);
                    float v1 = __expf(acc[mt][nt][2 * h + 1] * alpha);
                    rowsum += v0 + v1;
                    *(__half2*)&C[cbase + nt * 8] = __floats2half2_rn(v0, v1);
                }
                rowsum += __shfl_xor_sync(0xffffffffu, rowsum, 1);
                rowsum += __shfl_xor_sync(0xffffffffu, rowsum, 2);
                if (tig == 0)
                    Lp[(blockIdx.x * 2 + wg) * (long long)MALL
                       + blockIdx.z * (long long)NPIX + row] = rowsum;
            } else {
                float* C = (float*)Cv + (long long)blockIdx.z * sCz;
                float rs = inv[blockIdx.z * (long long)NPIX + row];
                #pragma unroll
                for (int nt = 0; nt < 8; nt++) {
                    float v0 = acc[mt][nt][2 * h]     * rs;
                    float v1 = acc[mt][nt][2 * h + 1] * rs;
                    *(float2*)&C[cbase + nt * 8] = make_float2(v0, v1);
                }
            }
        }
    }
}

// ---------------- rowsum inverse: inv[i] = 1 / sum_j Lp[j][i] ----------------
__global__ void rowsum_inv(const float* __restrict__ Lp, float* __restrict__ inv) {
    int i = blockIdx.x * 256 + threadIdx.x;
    float s = 0.f;
    #pragma unroll
    for (int j = 0; j < 64; j++) s += Lp[j * MALL + i];
    inv[i] = 1.0f / s;
}

// ---------------- legacy tf32 tensor-core GEMM (QKV / proj, proven, occ 2) ----------------
// OUTH: write __half output instead of float.
#define SMP 20
template<bool BIASC, bool BIASR, bool RESID, bool OUTH>
__global__ void __launch_bounds__(256, 2)
tcgemm(const float* __restrict__ A, int lda, long long sAz,
       const float* __restrict__ B, int ldb, long long sBz,
       void* __restrict__ Cv, int ldc, long long sCz,
       const float* __restrict__ biasc, const float* __restrict__ biasr,
       const float* __restrict__ resid, float alpha, int K)
{
    __shared__ float As[2][128][SMP];
    __shared__ float Bs[2][128][SMP];

    A += (long long)blockIdx.z * sAz;
    B += (long long)blockIdx.z * sBz;

    const int tid = threadIdx.x;
    const int m0 = blockIdx.y * 128, n0 = blockIdx.x * 128;

    const int arow = tid >> 2;
    const int ac   = (tid & 3) * 4;
    const float* Ag = A + (long long)(m0 + arow) * lda + ac;
    const float* Bg = B + (long long)(n0 + arow) * ldb + ac;

    const int w = tid >> 5, lane = tid & 31;
    const int wm = (w & 3) * 32, wn = (w >> 2) * 64;
    const int gid = lane >> 2, tg = lane & 3;

    float acc[2][8][4] = {};
    const int KT = K >> 4;

    {
        #pragma unroll
        for (int j = 0; j < 2; j++) {
            cp16g(&As[0][arow + 64 * j][ac], Ag + (long long)64 * j * lda);
            cp16g(&Bs[0][arow + 64 * j][ac], Bg + (long long)64 * j * ldb);
        }
        cp_commit();
    }

    for (int kt = 0; kt < KT; kt++) {
        cp_wait0();
        __syncthreads();
        if (kt + 1 < KT) {
            int buf = (kt + 1) & 1;
            long long ko = (long long)(kt + 1) * 16;
            #pragma unroll
            for (int j = 0; j < 2; j++) {
                cp16g(&As[buf][arow + 64 * j][ac], Ag + (long long)64 * j * lda + ko);
                cp16g(&Bs[buf][arow + 64 * j][ac], Bg + (long long)64 * j * ldb + ko);
            }
            cp_commit();
        }
        const int buf = kt & 1;
        const float (*as)[SMP] = As[buf];
        const float (*bs)[SMP] = Bs[buf];
        #pragma unroll
        for (int ks = 0; ks < 2; ks++) {
            const int k0 = ks * 8;
            unsigned a[2][4], b[8][2];
            #pragma unroll
            for (int mt = 0; mt < 2; mt++) {
                int r = wm + mt * 16 + gid;
                a[mt][0] = __float_as_uint(as[r][k0 + tg]);
                a[mt][1] = __float_as_uint(as[r + 8][k0 + tg]);
                a[mt][2] = __float_as_uint(as[r][k0 + tg + 4]);
                a[mt][3] = __float_as_uint(as[r + 8][k0 + tg + 4]);
            }
            #pragma unroll
            for (int nt = 0; nt < 8; nt++) {
                int c = wn + nt * 8 + gid;
                b[nt][0] = __float_as_uint(bs[c][k0 + tg]);
                b[nt][1] = __float_as_uint(bs[c][k0 + tg + 4]);
            }
            #pragma unroll
            for (int mt = 0; mt < 2; mt++)
                #pragma unroll
                for (int nt = 0; nt < 8; nt++)
                    mma_tf32(acc[mt][nt], a[mt], b[nt]);
        }
        __syncthreads();
    }

    #pragma unroll
    for (int mt = 0; mt < 2; mt++) {
        #pragma unroll
        for (int nt = 0; nt < 8; nt++) {
            int r0 = m0 + wm + mt * 16 + gid;
            int c0 = n0 + wn + nt * 8 + 2 * tg;
            #pragma unroll
            for (int h = 0; h < 2; h++) {
                int r = r0 + 8 * h;
                float v0 = acc[mt][nt][2 * h]     * alpha;
                float v1 = acc[mt][nt][2 * h + 1] * alpha;
                if (BIASC) { v0 += biasc[c0]; v1 += biasc[c0 + 1]; }
                if (BIASR) { float rb = biasr[r]; v0 += rb; v1 += rb; }
                long long off = (long long)r * ldc + c0;
                if (OUTH) {
                    __half* C = (__half*)Cv;
                    *(__half2*)&C[off] = __floats2half2_rn(v0, v1);
                } else {
                    float* C = (float*)Cv;
                    if (RESID) { v0 += resid[off]; v1 += resid[off + 1]; }
                    *(float2*)&C[off] = make_float2(v0, v1);
                }
            }
        }
    }
}

// ---------------- launch ----------------
extern "C" void kernel_launch(void* const* d_in, const int* in_sizes, int n_in,
                              void* d_out, int out_size) {
    const float* x     = (const float*)d_in[0];
    const float* gamma = (const float*)d_in[1];
    const float* beta  = (const float*)d_in[2];
    const float* wq    = (const float*)d_in[3];
    const float* bq    = (const float*)d_in[4];
    const float* wk    = (const float*)d_in[5];
    const float* bk    = (const float*)d_in[6];
    const float* wv    = (const float*)d_in[7];
    const float* bv    = (const float*)d_in[8];
    const float* wp    = (const float*)d_in[9];
    const float* bp    = (const float*)d_in[10];
    float* out = (float*)d_out;

    float *xn, *o, *wT, *Lp, *inv;
    __half *qh, *kh, *vth, *sh;
    cudaGetSymbolAddress((void**)&xn,  g_xn);
    cudaGetSymbolAddress((void**)&qh,  g_qh);
    cudaGetSymbolAddress((void**)&kh,  g_kh);
    cudaGetSymbolAddress((void**)&vth, g_vth);
    cudaGetSymbolAddress((void**)&sh,  g_sh);
    cudaGetSymbolAddress((void**)&o,   g_o);
    cudaGetSymbolAddress((void**)&wT,  g_wT);
    cudaGetSymbolAddress((void**)&Lp,  g_Lp);
    cudaGetSymbolAddress((void**)&inv, g_inv);

    // 1. GroupNorm
    gn_stats<<<BATCH * GRP, 256>>>(x);
    gn_apply<<<(MALL * CCH / 4) / 256, 256>>>(x, gamma, beta);

    // 2. transpose weights
    transpose_w<<<dim3(8, 8, 4), dim3(32, 32)>>>(wq, wk, wv, wp);

    // 3. Q / K (fp16 out), VT (fp16 out, produced transposed)
    tcgemm<true, false, false, true><<<dim3(2, 128, 1), 256>>>(
        xn, CCH, 0, wT + 0 * CCH * CCH, CCH, 0, qh, CCH, 0,
        bq, nullptr, nullptr, 1.0f, CCH);
    tcgemm<true, false, false, true><<<dim3(2, 128, 1), 256>>>(
        xn, CCH, 0, wT + 1 * CCH * CCH, CCH, 0, kh, CCH, 0,
        bk, nullptr, nullptr, 1.0f, CCH);
    tcgemm<false, true, false, true><<<dim3(MALL / 128, CCH / 128, 1), 256>>>(
        wT + 2 * CCH * CCH, CCH, 0, xn, CCH, 0, vth, MALL, 0,
        nullptr, bv, nullptr, 1.0f, CCH);

    // 4. S = exp(Q @ K^T / 16) in fp16, plus row-sum partials
    hgemm<1><<<dim3(NPIX / 128, NPIX / 128, BATCH), 256>>>(
        qh, CCH, (long long)NPIX * CCH,
        kh, CCH, (long long)NPIX * CCH,
        sh, NPIX, (long long)NPIX * NPIX,
        Lp, nullptr, 0.0625f, CCH);

    // 5. inv[row] = 1 / rowsum
    rowsum_inv<<<MALL / 256, 256>>>(Lp, inv);

    // 6. O = (S @ V) * inv   (fp16 inputs, fp32 out; K = 4096)
    hgemm<2><<<dim3(CCH / 128, NPIX / 128, BATCH), 256>>>(
        sh, NPIX, (long long)NPIX * NPIX,
        vth, MALL, (long long)NPIX,
        o, CCH, (long long)NPIX * CCH,
        nullptr, inv, 1.0f, NPIX);

    // 7. y = x + O @ wp + bp
    tcgemm<true, false, true, false><<<dim3(2, 128, 1), 256>>>(
        o, CCH, 0, wT + 3 * CCH * CCH, CCH, 0, out, CCH, 0,
        bp, nullptr, x, 1.0f, CCH);
}

// round 8
// speedup vs baseline: 8.0838x; 1.1503x over previous
#include <cuda_runtime.h>
#include <cuda_fp16.h>
#include <cstdint>

// Problem constants (fixed shapes from reference)
#define BATCH   4
#define NPIX    4096          // H*W = 64*64
#define CCH     256
#define GRP     8
#define GSIZE   32            // CCH / GRP
#define MALL    16384         // BATCH * NPIX

// -------- scratch (static device globals; no allocation) --------
__device__ float g_mean[BATCH * GRP];
__device__ float g_rstd[BATCH * GRP];
__device__ __half g_xnh[MALL * CCH];
__device__ __half g_qh[MALL * CCH];
__device__ __half g_kh[MALL * CCH];
__device__ __half g_vth[CCH * MALL];                      // V transposed (fp16): [256][16384]
__device__ __half g_oh[MALL * CCH];                       // attention output (fp16)
__device__ __half g_sh[(long long)BATCH * NPIX * NPIX];   // exp'd scores, fp16 (128 MB)
__device__ __half g_wTh[4 * CCH * CCH];                   // wq^T, wk^T, wv^T, wp^T (fp16)
__device__ float g_Lp[64 * MALL];                         // row-sum partials [64][16384]
__device__ float g_inv[MALL];                             // 1 / rowsum

// ---------------- GroupNorm statistics: one block per (b,g) ----------------
__global__ void gn_stats(const float* __restrict__ x) {
    int bg = blockIdx.x;            // 0..31
    int b = bg >> 3, g = bg & 7;
    const float* base = x + (long)b * NPIX * CCH + g * GSIZE;
    float s = 0.f, ss = 0.f;
    for (int i = threadIdx.x; i < NPIX * GSIZE; i += blockDim.x) {
        int p = i >> 5, c = i & 31;
        float v = base[(long)p * CCH + c];
        s += v; ss += v * v;
    }
    __shared__ float sh[16];
    #pragma unroll
    for (int o = 16; o > 0; o >>= 1) {
        s  += __shfl_xor_sync(0xffffffffu, s,  o);
        ss += __shfl_xor_sync(0xffffffffu, ss, o);
    }
    int w = threadIdx.x >> 5, l = threadIdx.x & 31;
    if (l == 0) { sh[w] = s; sh[8 + w] = ss; }
    __syncthreads();
    if (threadIdx.x == 0) {
        float S = 0.f, SS = 0.f;
        #pragma unroll
        for (int i = 0; i < 8; i++) { S += sh[i]; SS += sh[8 + i]; }
        const float invn = 1.0f / (NPIX * GSIZE);
        float mean = S * invn;
        float var  = SS * invn - mean * mean;
        g_mean[bg] = mean;
        g_rstd[bg] = rsqrtf(var + 1e-3f);
    }
}

// ---------------- GroupNorm apply: fp32 in, fp16 out ----------------
__global__ void gn_apply(const float* __restrict__ x,
                         const float* __restrict__ gamma,
                         const float* __restrict__ beta) {
    long i4 = (long)blockIdx.x * blockDim.x + threadIdx.x;   // float4 index
    float4 xv = ((const float4*)x)[i4];
    int c0 = (int)(i4 & 63) * 4;        // 64 float4 per channel row
    long row = i4 >> 6;                 // pixel index 0..16383
    int b = (int)(row >> 12);           // /4096
    int bg = b * 8 + (c0 >> 5);
    float m = g_mean[bg], r = g_rstd[bg];
    __half2 h0 = __floats2half2_rn((xv.x - m) * r * gamma[c0 + 0] + beta[c0 + 0],
                                   (xv.y - m) * r * gamma[c0 + 1] + beta[c0 + 1]);
    __half2 h1 = __floats2half2_rn((xv.z - m) * r * gamma[c0 + 2] + beta[c0 + 2],
                                   (xv.w - m) * r * gamma[c0 + 3] + beta[c0 + 3]);
    uint2 pk; pk.x = *(unsigned*)&h0; pk.y = *(unsigned*)&h1;
    ((uint2*)g_xnh)[i4] = pk;
}

// ---------------- transpose the four 256x256 weight matrices (fp16 out) ----------------
__global__ void transpose_w(const float* __restrict__ wq, const float* __restrict__ wk,
                            const float* __restrict__ wv, const float* __restrict__ wp) {
    __shared__ float t[32][33];
    int mat = blockIdx.z;
    const float* src = (mat == 0) ? wq : (mat == 1) ? wk : (mat == 2) ? wv : wp;
    int x0 = blockIdx.x * 32, y0 = blockIdx.y * 32;
    t[threadIdx.y][threadIdx.x] = src[(y0 + threadIdx.y) * CCH + x0 + threadIdx.x];
    __syncthreads();
    g_wTh[mat * CCH * CCH + (x0 + threadIdx.y) * CCH + y0 + threadIdx.x] =
        __float2half_rn(t[threadIdx.x][threadIdx.y]);
}

// ---------------- cp.async / mma / ldmatrix helpers ----------------
__device__ __forceinline__ void cp16g(void* smem, const void* gmem) {
    unsigned s = (unsigned)__cvta_generic_to_shared(smem);
    asm volatile("cp.async.cg.shared.global [%0], [%1], 16;\n" :: "r"(s), "l"(gmem));
}
__device__ __forceinline__ void cp_commit() { asm volatile("cp.async.commit_group;\n"); }
__device__ __forceinline__ void cp_wait0() { asm volatile("cp.async.wait_group 0;\n"); }

__device__ __forceinline__ void mma_f16(float* c, const unsigned* a, const unsigned* b) {
    asm volatile("mma.sync.aligned.m16n8k16.row.col.f32.f16.f16.f32 "
        "{%0,%1,%2,%3}, {%4,%5,%6,%7}, {%8,%9}, {%0,%1,%2,%3};"
        : "+f"(c[0]), "+f"(c[1]), "+f"(c[2]), "+f"(c[3])
        : "r"(a[0]), "r"(a[1]), "r"(a[2]), "r"(a[3]), "r"(b[0]), "r"(b[1]));
}
__device__ __forceinline__ void ldsm4(unsigned* r, uint32_t addr) {
    asm volatile("ldmatrix.sync.aligned.m8n8.x4.shared.b16 {%0,%1,%2,%3}, [%4];"
        : "=r"(r[0]), "=r"(r[1]), "=r"(r[2]), "=r"(r[3]) : "r"(addr));
}

// ================= unified fp16 GEMM: C = f(A @ B^T), CTA 128x128, warp 32x64 =================
// A: [M,K] halves lda, B: [N,K] halves ldb (dot over K). Batched via blockIdx.z.
// EPI 0: C(half)  = acc + biasc[col]                       (Q, K projections)
// EPI 1: C(half)  = acc + biasr[row]                       (VT projection)
// EPI 2: C(half)  = exp(alpha*acc); Lp partial row sums    (scores)
// EPI 3: C(half)  = acc * inv[row]                         (attn @ V)
// EPI 4: C(float) = acc + biasc[col] + resid[off]          (final projection)
#define HP 40                      // smem pitch in halves (32 data + 8 pad) -> 80 B rows
template<int EPI>
__global__ void __launch_bounds__(256, 2)
hgemm(const __half* __restrict__ A, int lda, long long sAz,
      const __half* __restrict__ B, int ldb, long long sBz,
      void* __restrict__ Cv, int ldc, long long sCz,
      const float* __restrict__ biasc, const float* __restrict__ biasr,
      const float* __restrict__ resid,
      float* __restrict__ Lp, const float* __restrict__ inv,
      float alpha, int K)
{
    __shared__ __align__(16) __half As[2][128 * HP];
    __shared__ __align__(16) __half Bs[2][128 * HP];

    A += (long long)blockIdx.z * sAz;
    B += (long long)blockIdx.z * sBz;

    const int tid = threadIdx.x;
    const int w = tid >> 5, lane = tid & 31;
    const int gid = lane >> 2, tig = lane & 3;
    const int wm = (w & 3) * 32;        // 4 m-warps
    const int wn = (w >> 2) * 64;       // 2 n-warps
    const int wg = w >> 2;
    const long long m0 = (long long)blockIdx.y * 128;
    const long long n0 = (long long)blockIdx.x * 128;

    // loader coords: each thread copies 2x16B per matrix per stage
    const int lr = tid >> 1;            // row 0..127
    const int lc = (tid & 1) * 16;      // half-offset 0 or 16
    const __half* Ag = A + (m0 + lr) * lda + lc;
    const __half* Bg = B + (n0 + lr) * (long long)ldb + lc;
    __half* Asd = &As[0][lr * HP + lc];
    __half* Bsd = &Bs[0][lr * HP + lc];

    // ldmatrix lane address components (in halves)
    const int a_row = wm + (lane & 15);
    const int a_col = (lane >> 4) << 3;
    const int b_row = wn + ((lane >> 4) << 3) + (lane & 7);
    const int b_col = ((lane >> 3) & 1) << 3;
    const uint32_t asB = (uint32_t)__cvta_generic_to_shared(&As[0][0]);
    const uint32_t bsB = (uint32_t)__cvta_generic_to_shared(&Bs[0][0]);

    float acc[2][8][4] = {};
    const int KT = K >> 5;              // slabs of 32 halves

    // prologue: stage 0
    cp16g(Asd, Ag);            cp16g(Asd + 8, Ag + 8);
    cp16g(Bsd, Bg);            cp16g(Bsd + 8, Bg + 8);
    cp_commit();

    for (int kt = 0; kt < KT; kt++) {
        cp_wait0();
        __syncthreads();
        if (kt + 1 < KT) {
            int buf = (kt + 1) & 1;
            long long ko = (long long)(kt + 1) * 32;
            __half* ad = Asd + buf * 128 * HP;
            __half* bd = Bsd + buf * 128 * HP;
            cp16g(ad, Ag + ko);        cp16g(ad + 8, Ag + ko + 8);
            cp16g(bd, Bg + ko);        cp16g(bd + 8, Bg + ko + 8);
            cp_commit();
        }
        const uint32_t asb = asB + (kt & 1) * (128 * HP * 2);
        const uint32_t bsb = bsB + (kt & 1) * (128 * HP * 2);
        #pragma unroll
        for (int kk = 0; kk < 32; kk += 16) {
            unsigned a[2][4], b[4][4];
            #pragma unroll
            for (int mt = 0; mt < 2; mt++)
                ldsm4(a[mt], asb + ((a_row + mt * 16) * HP + kk + a_col) * 2);
            #pragma unroll
            for (int p = 0; p < 4; p++)
                ldsm4(b[p], bsb + ((b_row + p * 16) * HP + kk + b_col) * 2);
            #pragma unroll
            for (int mt = 0; mt < 2; mt++)
                #pragma unroll
                for (int nt = 0; nt < 8; nt++)
                    mma_f16(acc[mt][nt], a[mt], &b[nt >> 1][(nt & 1) * 2]);
        }
        __syncthreads();
    }

    // ---------------- epilogue ----------------
    #pragma unroll
    for (int mt = 0; mt < 2; mt++) {
        #pragma unroll
        for (int h = 0; h < 2; h++) {
            long long row = m0 + wm + mt * 16 + gid + 8 * h;
            long long cbase = row * ldc + n0 + wn + 2 * tig;
            if (EPI == 2) {
                __half* C = (__half*)Cv + (long long)blockIdx.z * sCz;
                float rowsum = 0.f;
                #pragma unroll
                for (int nt = 0; nt < 8; nt++) {
                    float v0 = __expf(acc[mt][nt][2 * h]     * alpha);
                    float v1 = __expf(acc[mt][nt][2 * h + 1] * alpha);
                    rowsum += v0 + v1;
                    *(__half2*)&C[cbase + nt * 8] = __floats2half2_rn(v0, v1);
                }
                rowsum += __shfl_xor_sync(0xffffffffu, rowsum, 1);
                rowsum += __shfl_xor_sync(0xffffffffu, rowsum, 2);
                if (tig == 0)
                    Lp[(blockIdx.x * 2 + wg) * (long long)MALL
                       + blockIdx.z * (long long)NPIX + row] = rowsum;
            } else if (EPI == 3) {
                __half* C = (__half*)Cv + (long long)blockIdx.z * sCz;
                float rs = inv[blockIdx.z * (long long)NPIX + row];
                #pragma unroll
                for (int nt = 0; nt < 8; nt++)
                    *(__half2*)&C[cbase + nt * 8] =
                        __floats2half2_rn(acc[mt][nt][2 * h] * rs,
                                          acc[mt][nt][2 * h + 1] * rs);
            } else if (EPI == 4) {
                float* C = (float*)Cv;
                #pragma unroll
                for (int nt = 0; nt < 8; nt++) {
                    long long c0 = n0 + wn + nt * 8 + 2 * tig;
                    long long off = cbase + nt * 8;
                    float v0 = acc[mt][nt][2 * h]     + biasc[c0]     + resid[off];
                    float v1 = acc[mt][nt][2 * h + 1] + biasc[c0 + 1] + resid[off + 1];
                    *(float2*)&C[off] = make_float2(v0, v1);
                }
            } else if (EPI == 0) {
                __half* C = (__half*)Cv;
                #pragma unroll
                for (int nt = 0; nt < 8; nt++) {
                    long long c0 = n0 + wn + nt * 8 + 2 * tig;
                    *(__half2*)&C[cbase + nt * 8] =
                        __floats2half2_rn(acc[mt][nt][2 * h] + biasc[c0],
                                          acc[mt][nt][2 * h + 1] + biasc[c0 + 1]);
                }
            } else {  // EPI 1: row bias
                __half* C = (__half*)Cv;
                float rb = biasr[row];
                #pragma unroll
                for (int nt = 0; nt < 8; nt++)
                    *(__half2*)&C[cbase + nt * 8] =
                        __floats2half2_rn(acc[mt][nt][2 * h] + rb,
                                          acc[mt][nt][2 * h + 1] + rb);
            }
        }
    }
}

// ---------------- rowsum inverse: inv[i] = 1 / sum_j Lp[j][i] ----------------
__global__ void rowsum_inv(const float* __restrict__ Lp, float* __restrict__ inv) {
    int i = blockIdx.x * 256 + threadIdx.x;
    float s = 0.f;
    #pragma unroll
    for (int j = 0; j < 64; j++) s += Lp[j * MALL + i];
    inv[i] = 1.0f / s;
}

// ---------------- launch ----------------
extern "C" void kernel_launch(void* const* d_in, const int* in_sizes, int n_in,
                              void* d_out, int out_size) {
    const float* x     = (const float*)d_in[0];
    const float* gamma = (const float*)d_in[1];
    const float* beta  = (const float*)d_in[2];
    const float* wq    = (const float*)d_in[3];
    const float* bq    = (const float*)d_in[4];
    const float* wk    = (const float*)d_in[5];
    const float* bk    = (const float*)d_in[6];
    const float* wv    = (const float*)d_in[7];
    const float* bv    = (const float*)d_in[8];
    const float* wp    = (const float*)d_in[9];
    const float* bp    = (const float*)d_in[10];
    float* out = (float*)d_out;

    float *Lp, *inv;
    __half *xnh, *qh, *kh, *vth, *oh, *sh, *wTh;
    cudaGetSymbolAddress((void**)&xnh, g_xnh);
    cudaGetSymbolAddress((void**)&qh,  g_qh);
    cudaGetSymbolAddress((void**)&kh,  g_kh);
    cudaGetSymbolAddress((void**)&vth, g_vth);
    cudaGetSymbolAddress((void**)&oh,  g_oh);
    cudaGetSymbolAddress((void**)&sh,  g_sh);
    cudaGetSymbolAddress((void**)&wTh, g_wTh);
    cudaGetSymbolAddress((void**)&Lp,  g_Lp);
    cudaGetSymbolAddress((void**)&inv, g_inv);

    // 1. GroupNorm -> fp16 xn
    gn_stats<<<BATCH * GRP, 256>>>(x);
    gn_apply<<<(MALL * CCH / 4) / 256, 256>>>(x, gamma, beta);

    // 2. transpose weights -> fp16
    transpose_w<<<dim3(8, 8, 4), dim3(32, 32)>>>(wq, wk, wv, wp);

    // 3. Q / K (fp16), VT (fp16, produced transposed)
    hgemm<0><<<dim3(2, 128, 1), 256>>>(
        xnh, CCH, 0, wTh + 0 * CCH * CCH, CCH, 0, qh, CCH, 0,
        bq, nullptr, nullptr, nullptr, nullptr, 1.0f, CCH);
    hgemm<0><<<dim3(2, 128, 1), 256>>>(
        xnh, CCH, 0, wTh + 1 * CCH * CCH, CCH, 0, kh, CCH, 0,
        bk, nullptr, nullptr, nullptr, nullptr, 1.0f, CCH);
    hgemm<1><<<dim3(MALL / 128, CCH / 128, 1), 256>>>(
        wTh + 2 * CCH * CCH, CCH, 0, xnh, CCH, 0, vth, MALL, 0,
        nullptr, bv, nullptr, nullptr, nullptr, 1.0f, CCH);

    // 4. S = exp(Q @ K^T / 16) in fp16, plus row-sum partials
    hgemm<2><<<dim3(NPIX / 128, NPIX / 128, BATCH), 256>>>(
        qh, CCH, (long long)NPIX * CCH,
        kh, CCH, (long long)NPIX * CCH,
        sh, NPIX, (long long)NPIX * NPIX,
        nullptr, nullptr, nullptr, Lp, nullptr, 0.0625f, CCH);

    // 5. inv[row] = 1 / rowsum
    rowsum_inv<<<MALL / 256, 256>>>(Lp, inv);

    // 6. O = (S @ V) * inv  -> fp16   (K = 4096)
    hgemm<3><<<dim3(CCH / 128, NPIX / 128, BATCH), 256>>>(
        sh, NPIX, (long long)NPIX * NPIX,
        vth, MALL, (long long)NPIX,
        oh, CCH, (long long)NPIX * CCH,
        nullptr, nullptr, nullptr, nullptr, inv, 1.0f, NPIX);

    // 7. y = x + O @ wp + bp   (fp32 out)
    hgemm<4><<<dim3(2, 128, 1), 256>>>(
        oh, CCH, 0, wTh + 3 * CCH * CCH, CCH, 0, out, CCH, 0,
        bp, nullptr, x, nullptr, nullptr, 1.0f, CCH);
}

// round 9
// speedup vs baseline: 8.4371x; 1.0437x over previous
#include <cuda_runtime.h>
#include <cuda_fp16.h>
#include <cstdint>

// Problem constants (fixed shapes from reference)
#define BATCH   4
#define NPIX    4096          // H*W = 64*64
#define CCH     256
#define GRP     8
#define GSIZE   32            // CCH / GRP
#define MALL    16384         // BATCH * NPIX

// -------- scratch (static device globals; no allocation) --------
__device__ float g_ps [32 * 8];                           // GN partial sums
__device__ float g_ps2[32 * 8];                           // GN partial sumsq
__device__ float g_mean[BATCH * GRP];
__device__ float g_rstd[BATCH * GRP];
__device__ __half g_xnh[MALL * CCH];
__device__ __half g_qkh[2 * MALL * CCH];                  // Q then K (fp16)
__device__ __half g_vth[CCH * MALL];                      // V transposed (fp16): [256][16384]
__device__ __half g_oh[MALL * CCH];                       // attention output (fp16)
__device__ __half g_sh[(long long)BATCH * NPIX * NPIX];   // exp'd scores, fp16 (128 MB)
__device__ __half g_wTh[4 * CCH * CCH];                   // wq^T, wk^T, wv^T, wp^T (fp16)
__device__ float g_Lp[64 * MALL];                         // row-sum partials [64][16384]
__device__ float g_inv[MALL];                             // 1 / rowsum

// ---------------- GroupNorm partial stats: one block per (bg, slice) ----------------
__global__ void gn_part(const float* __restrict__ x) {
    int bg = blockIdx.x;            // 0..31
    int sl = blockIdx.y;            // 0..7
    int b = bg >> 3, g = bg & 7;
    const float* base = x + (long)b * NPIX * CCH + g * GSIZE;
    float s = 0.f, ss = 0.f;
    for (int i = threadIdx.x; i < 512 * GSIZE; i += blockDim.x) {
        int p = sl * 512 + (i >> 5), c = i & 31;
        float v = base[(long)p * CCH + c];
        s += v; ss += v * v;
    }
    __shared__ float sh[16];
    #pragma unroll
    for (int o = 16; o > 0; o >>= 1) {
        s  += __shfl_xor_sync(0xffffffffu, s,  o);
        ss += __shfl_xor_sync(0xffffffffu, ss, o);
    }
    int w = threadIdx.x >> 5, l = threadIdx.x & 31;
    if (l == 0) { sh[w] = s; sh[8 + w] = ss; }
    __syncthreads();
    if (threadIdx.x == 0) {
        float S = 0.f, SS = 0.f;
        #pragma unroll
        for (int i = 0; i < 8; i++) { S += sh[i]; SS += sh[8 + i]; }
        g_ps [bg * 8 + sl] = S;
        g_ps2[bg * 8 + sl] = SS;
    }
}
__global__ void gn_final() {
    int bg = threadIdx.x;   // 32 threads
    float S = 0.f, SS = 0.f;
    #pragma unroll
    for (int i = 0; i < 8; i++) { S += g_ps[bg * 8 + i]; SS += g_ps2[bg * 8 + i]; }
    const float invn = 1.0f / (NPIX * GSIZE);
    float mean = S * invn;
    float var  = SS * invn - mean * mean;
    g_mean[bg] = mean;
    g_rstd[bg] = rsqrtf(var + 1e-3f);
}

// ---------------- GroupNorm apply: fp32 in, fp16 out ----------------
__global__ void gn_apply(const float* __restrict__ x,
                         const float* __restrict__ gamma,
                         const float* __restrict__ beta) {
    long i4 = (long)blockIdx.x * blockDim.x + threadIdx.x;   // float4 index
    float4 xv = ((const float4*)x)[i4];
    int c0 = (int)(i4 & 63) * 4;        // 64 float4 per channel row
    long row = i4 >> 6;                 // pixel index 0..16383
    int b = (int)(row >> 12);           // /4096
    int bg = b * 8 + (c0 >> 5);
    float m = g_mean[bg], r = g_rstd[bg];
    __half2 h0 = __floats2half2_rn((xv.x - m) * r * gamma[c0 + 0] + beta[c0 + 0],
                                   (xv.y - m) * r * gamma[c0 + 1] + beta[c0 + 1]);
    __half2 h1 = __floats2half2_rn((xv.z - m) * r * gamma[c0 + 2] + beta[c0 + 2],
                                   (xv.w - m) * r * gamma[c0 + 3] + beta[c0 + 3]);
    uint2 pk; pk.x = *(unsigned*)&h0; pk.y = *(unsigned*)&h1;
    ((uint2*)g_xnh)[i4] = pk;
}

// ---------------- transpose the four 256x256 weight matrices (fp16 out) ----------------
__global__ void transpose_w(const float* __restrict__ wq, const float* __restrict__ wk,
                            const float* __restrict__ wv, const float* __restrict__ wp) {
    __shared__ float t[32][33];
    int mat = blockIdx.z;
    const float* src = (mat == 0) ? wq : (mat == 1) ? wk : (mat == 2) ? wv : wp;
    int x0 = blockIdx.x * 32, y0 = blockIdx.y * 32;
    t[threadIdx.y][threadIdx.x] = src[(y0 + threadIdx.y) * CCH + x0 + threadIdx.x];
    __syncthreads();
    g_wTh[mat * CCH * CCH + (x0 + threadIdx.y) * CCH + y0 + threadIdx.x] =
        __float2half_rn(t[threadIdx.x][threadIdx.y]);
}

// ---------------- cp.async / mma / ldmatrix helpers ----------------
__device__ __forceinline__ void cp16g(void* smem, const void* gmem) {
    unsigned s = (unsigned)__cvta_generic_to_shared(smem);
    asm volatile("cp.async.cg.shared.global [%0], [%1], 16;\n" :: "r"(s), "l"(gmem));
}
__device__ __forceinline__ void cp_commit() { asm volatile("cp.async.commit_group;\n"); }
__device__ __forceinline__ void cp_wait0() { asm volatile("cp.async.wait_group 0;\n"); }

__device__ __forceinline__ void mma_f16(float* c, const unsigned* a, const unsigned* b) {
    asm volatile("mma.sync.aligned.m16n8k16.row.col.f32.f16.f16.f32 "
        "{%0,%1,%2,%3}, {%4,%5,%6,%7}, {%8,%9}, {%0,%1,%2,%3};"
        : "+f"(c[0]), "+f"(c[1]), "+f"(c[2]), "+f"(c[3])
        : "r"(a[0]), "r"(a[1]), "r"(a[2]), "r"(a[3]), "r"(b[0]), "r"(b[1]));
}
__device__ __forceinline__ void ldsm4(unsigned* r, uint32_t addr) {
    asm volatile("ldmatrix.sync.aligned.m8n8.x4.shared.b16 {%0,%1,%2,%3}, [%4];"
        : "=r"(r[0]), "=r"(r[1]), "=r"(r[2]), "=r"(r[3]) : "r"(addr));
}

// ================= unified fp16 GEMM: C = f(A @ B^T), CTA 128x128, warp 32x64 =================
// A: [M,K] halves lda, B: [N,K] halves ldb (dot over K). Batched via blockIdx.z.
// K-slab = 64 halves, smem pitch 72 halves (144 B), double-buffered dynamic smem.
// EPI 0: C(half)  = acc + bias[col]; bias = biasc (z=0) or biasr (z=1)   (Q & K merged)
// EPI 1: C(half)  = acc + biasr[row]                                     (VT projection)
// EPI 2: C(half)  = exp(alpha*acc); Lp partial row sums                  (scores)
// EPI 3: C(half)  = acc * inv[row]                                       (attn @ V)
// EPI 4: C(float) = acc + biasc[col] + resid[off]                        (final projection)
#define HP 72                       // smem pitch in halves (64 data + 8 pad)
#define SSH (128 * HP)              // halves per matrix per stage
template<int EPI>
__global__ void __launch_bounds__(256, 2)
hgemm(const __half* __restrict__ A, int lda, long long sAz,
      const __half* __restrict__ B, int ldb, long long sBz,
      void* __restrict__ Cv, int ldc, long long sCz,
      const float* __restrict__ biasc, const float* __restrict__ biasr,
      const float* __restrict__ resid,
      float* __restrict__ Lp, const float* __restrict__ inv,
      float alpha, int K)
{
    extern __shared__ __align__(16) __half dsm[];   // [2][A:SSH | B:SSH]

    A += (long long)blockIdx.z * sAz;
    B += (long long)blockIdx.z * sBz;

    const int tid = threadIdx.x;
    const int w = tid >> 5, lane = tid & 31;
    const int gid = lane >> 2, tig = lane & 3;
    const int wm = (w & 3) * 32;        // 4 m-warps
    const int wn = (w >> 2) * 64;       // 2 n-warps
    const int wg = w >> 2;
    const long long m0 = (long long)blockIdx.y * 128;
    const long long n0 = (long long)blockIdx.x * 128;

    // loader coords: each thread copies 4x16B per matrix per stage
    const int lr = tid >> 1;            // row 0..127
    const int lc = (tid & 1) * 32;      // half-offset 0 or 32
    const __half* Ag = A + (m0 + lr) * lda + lc;
    const __half* Bg = B + (n0 + lr) * (long long)ldb + lc;
    __half* Asd = dsm + lr * HP + lc;
    __half* Bsd = Asd + SSH;

    // ldmatrix lane address components (in halves)
    const int a_row = wm + (lane & 15);
    const int a_col = (lane >> 4) << 3;
    const int b_row = wn + ((lane >> 4) << 3) + (lane & 7);
    const int b_col = ((lane >> 3) & 1) << 3;
    const uint32_t smB = (uint32_t)__cvta_generic_to_shared(dsm);

    float acc[2][8][4] = {};
    const int KT = K >> 6;              // slabs of 64 halves

    // prologue: stage 0
    #pragma unroll
    for (int j = 0; j < 4; j++) { cp16g(Asd + 8 * j, Ag + 8 * j); }
    #pragma unroll
    for (int j = 0; j < 4; j++) { cp16g(Bsd + 8 * j, Bg + 8 * j); }
    cp_commit();

    for (int kt = 0; kt < KT; kt++) {
        cp_wait0();
        __syncthreads();
        if (kt + 1 < KT) {
            int buf = (kt + 1) & 1;
            long long ko = (long long)(kt + 1) * 64;
            __half* ad = Asd + buf * 2 * SSH;
            __half* bd = Bsd + buf * 2 * SSH;
            #pragma unroll
            for (int j = 0; j < 4; j++) { cp16g(ad + 8 * j, Ag + ko + 8 * j); }
            #pragma unroll
            for (int j = 0; j < 4; j++) { cp16g(bd + 8 * j, Bg + ko + 8 * j); }
            cp_commit();
        }
        const uint32_t asb = smB + (kt & 1) * (2 * SSH * 2);
        const uint32_t bsb = asb + SSH * 2;
        #pragma unroll
        for (int kk = 0; kk < 64; kk += 16) {
            unsigned a[2][4], b[4][4];
            #pragma unroll
            for (int mt = 0; mt < 2; mt++)
                ldsm4(a[mt], asb + ((a_row + mt * 16) * HP + kk + a_col) * 2);
            #pragma unroll
            for (int p = 0; p < 4; p++)
                ldsm4(b[p], bsb + ((b_row + p * 16) * HP + kk + b_col) * 2);
            #pragma unroll
            for (int mt = 0; mt < 2; mt++)
                #pragma unroll
                for (int nt = 0; nt < 8; nt++)
                    mma_f16(acc[mt][nt], a[mt], &b[nt >> 1][(nt & 1) * 2]);
        }
        __syncthreads();
    }

    // ---------------- epilogue ----------------
    #pragma unroll
    for (int mt = 0; mt < 2; mt++) {
        #pragma unroll
        for (int h = 0; h < 2; h++) {
            long long row = m0 + wm + mt * 16 + gid + 8 * h;
            long long cbase = row * ldc + n0 + wn + 2 * tig;
            if (EPI == 2) {
                __half* C = (__half*)Cv + (long long)blockIdx.z * sCz;
                float rowsum = 0.f;
                #pragma unroll
                for (int nt = 0; nt < 8; nt++) {
                    float v0 = __expf(acc[mt][nt][2 * h]     * alpha);
                    float v1 = __expf(acc[mt][nt][2 * h + 1] * alpha);
                    rowsum += v0 + v1;
                    *(__half2*)&C[cbase + nt * 8] = __floats2half2_rn(v0, v1);
                }
                rowsum += __shfl_xor_sync(0xffffffffu, rowsum, 1);
                rowsum += __shfl_xor_sync(0xffffffffu, rowsum, 2);
                if (tig == 0)
                    Lp[(blockIdx.x * 2 + wg) * (long long)MALL
                       + blockIdx.z * (long long)NPIX + row] = rowsum;
            } else if (EPI == 3) {
                __half* C = (__half*)Cv + (long long)blockIdx.z * sCz;
                float rs = inv[blockIdx.z * (long long)NPIX + row];
                #pragma unroll
                for (int nt = 0; nt < 8; nt++)
                    *(__half2*)&C[cbase + nt * 8] =
                        __floats2half2_rn(acc[mt][nt][2 * h] * rs,
                                          acc[mt][nt][2 * h + 1] * rs);
            } else if (EPI == 4) {
                float* C = (float*)Cv;
                #pragma unroll
                for (int nt = 0; nt < 8; nt++) {
                    long long c0 = n0 + wn + nt * 8 + 2 * tig;
                    long long off = cbase + nt * 8;
                    float v0 = acc[mt][nt][2 * h]     + biasc[c0]     + resid[off];
                    float v1 = acc[mt][nt][2 * h + 1] + biasc[c0 + 1] + resid[off + 1];
                    *(float2*)&C[off] = make_float2(v0, v1);
                }
            } else if (EPI == 0) {
                __half* C = (__half*)Cv + (long long)blockIdx.z * sCz;
                const float* bc = blockIdx.z ? biasr : biasc;   // biasr slot carries bk
                #pragma unroll
                for (int nt = 0; nt < 8; nt++) {
                    long long c0 = n0 + wn + nt * 8 + 2 * tig;
                    *(__half2*)&C[cbase + nt * 8] =
                        __floats2half2_rn(acc[mt][nt][2 * h] + bc[c0],
                                          acc[mt][nt][2 * h + 1] + bc[c0 + 1]);
                }
            } else {  // EPI 1: row bias
                __half* C = (__half*)Cv;
                float rb = biasr[row];
                #pragma unroll
                for (int nt = 0; nt < 8; nt++)
                    *(__half2*)&C[cbase + nt * 8] =
                        __floats2half2_rn(acc[mt][nt][2 * h] + rb,
                                          acc[mt][nt][2 * h + 1] + rb);
            }
        }
    }
}

// ---------------- rowsum inverse: inv[i] = 1 / sum_j Lp[j][i] ----------------
__global__ void rowsum_inv(const float* __restrict__ Lp, float* __restrict__ inv) {
    int i = blockIdx.x * 256 + threadIdx.x;
    float s = 0.f;
    #pragma unroll
    for (int j = 0; j < 64; j++) s += Lp[j * MALL + i];
    inv[i] = 1.0f / s;
}

// ---------------- launch ----------------
extern "C" void kernel_launch(void* const* d_in, const int* in_sizes, int n_in,
                              void* d_out, int out_size) {
    const float* x     = (const float*)d_in[0];
    const float* gamma = (const float*)d_in[1];
    const float* beta  = (const float*)d_in[2];
    const float* wq    = (const float*)d_in[3];
    const float* bq    = (const float*)d_in[4];
    const float* wk    = (const float*)d_in[5];
    const float* bk    = (const float*)d_in[6];
    const float* wv    = (const float*)d_in[7];
    const float* bv    = (const float*)d_in[8];
    const float* wp    = (const float*)d_in[9];
    const float* bp    = (const float*)d_in[10];
    float* out = (float*)d_out;

    float *Lp, *inv;
    __half *xnh, *qkh, *vth, *oh, *sh, *wTh;
    cudaGetSymbolAddress((void**)&xnh, g_xnh);
    cudaGetSymbolAddress((void**)&qkh, g_qkh);
    cudaGetSymbolAddress((void**)&vth, g_vth);
    cudaGetSymbolAddress((void**)&oh,  g_oh);
    cudaGetSymbolAddress((void**)&sh,  g_sh);
    cudaGetSymbolAddress((void**)&wTh, g_wTh);
    cudaGetSymbolAddress((void**)&Lp,  g_Lp);
    cudaGetSymbolAddress((void**)&inv, g_inv);
    __half* qh = qkh;
    __half* kh = qkh + (long long)MALL * CCH;

    const int SMB = 2 * 2 * SSH * 2;   // 73,728 B dynamic smem
    cudaFuncSetAttribute(hgemm<0>, cudaFuncAttributeMaxDynamicSharedMemorySize, SMB);
    cudaFuncSetAttribute(hgemm<1>, cudaFuncAttributeMaxDynamicSharedMemorySize, SMB);
    cudaFuncSetAttribute(hgemm<2>, cudaFuncAttributeMaxDynamicSharedMemorySize, SMB);
    cudaFuncSetAttribute(hgemm<3>, cudaFuncAttributeMaxDynamicSharedMemorySize, SMB);
    cudaFuncSetAttribute(hgemm<4>, cudaFuncAttributeMaxDynamicSharedMemorySize, SMB);

    // 1. GroupNorm -> fp16 xn
    gn_part<<<dim3(BATCH * GRP, 8), 256>>>(x);
    gn_final<<<1, 32>>>();
    gn_apply<<<(MALL * CCH / 4) / 256, 256>>>(x, gamma, beta);

    // 2. transpose weights -> fp16
    transpose_w<<<dim3(8, 8, 4), dim3(32, 32)>>>(wq, wk, wv, wp);

    // 3. Q & K (merged, grid.z selects), VT (produced transposed)
    hgemm<0><<<dim3(2, 128, 2), 256, SMB>>>(
        xnh, CCH, 0, wTh, CCH, (long long)CCH * CCH, qkh, CCH, (long long)MALL * CCH,
        bq, bk, nullptr, nullptr, nullptr, 1.0f, CCH);
    hgemm<1><<<dim3(MALL / 128, CCH / 128, 1), 256, SMB>>>(
        wTh + 2 * CCH * CCH, CCH, 0, xnh, CCH, 0, vth, MALL, 0,
        nullptr, bv, nullptr, nullptr, nullptr, 1.0f, CCH);

    // 4. S = exp(Q @ K^T / 16) in fp16, plus row-sum partials
    hgemm<2><<<dim3(NPIX / 128, NPIX / 128, BATCH), 256, SMB>>>(
        qh, CCH, (long long)NPIX * CCH,
        kh, CCH, (long long)NPIX * CCH,
        sh, NPIX, (long long)NPIX * NPIX,
        nullptr, nullptr, nullptr, Lp, nullptr, 0.0625f, CCH);

    // 5. inv[row] = 1 / rowsum
    rowsum_inv<<<MALL / 256, 256>>>(Lp, inv);

    // 6. O = (S @ V) * inv  -> fp16   (K = 4096)
    hgemm<3><<<dim3(CCH / 128, NPIX / 128, BATCH), 256, SMB>>>(
        sh, NPIX, (long long)NPIX * NPIX,
        vth, MALL, (long long)NPIX,
        oh, CCH, (long long)NPIX * CCH,
        nullptr, nullptr, nullptr, nullptr, inv, 1.0f, NPIX);

    // 7. y = x + O @ wp + bp   (fp32 out)
    hgemm<4><<<dim3(2, 128, 1), 256, SMB>>>(
        oh, CCH, 0, wTh + 3 * CCH * CCH, CCH, 0, out, CCH, 0,
        bp, nullptr, x, nullptr, nullptr, 1.0f, CCH);
}

// round 10
// speedup vs baseline: 8.4694x; 1.0038x over previous
#include <cuda_runtime.h>
#include <cuda_fp16.h>
#include <cstdint>

// Problem constants (fixed shapes from reference)
#define BATCH   4
#define NPIX    4096          // H*W = 64*64
#define CCH     256
#define GRP     8
#define GSIZE   32            // CCH / GRP
#define MALL    16384         // BATCH * NPIX

// -------- scratch (static device globals; no allocation) --------
__device__ float g_ps [32 * 8];                           // GN partial sums
__device__ float g_ps2[32 * 8];                           // GN partial sumsq
__device__ float g_mean[BATCH * GRP];
__device__ float g_rstd[BATCH * GRP];
__device__ __half g_xnh[MALL * CCH];
__device__ __half g_qkh[2 * MALL * CCH];                  // Q then K (fp16)
__device__ __half g_vth[CCH * MALL];                      // V transposed (fp16): [256][16384]
__device__ __half g_oh[MALL * CCH];                       // attention output (fp16)
__device__ __half g_sh[(long long)BATCH * NPIX * NPIX];   // exp'd scores, fp16 (128 MB)
__device__ __half g_wTh[4 * CCH * CCH];                   // wq^T, wk^T, wv^T, wp^T (fp16)
__device__ float g_Lp[64 * MALL];                         // row-sum partials [64][16384]
__device__ float g_inv[MALL];                             // 1 / rowsum

// ---------------- GroupNorm partial stats: one block per (bg, slice) ----------------
__global__ void gn_part(const float* __restrict__ x) {
    int bg = blockIdx.x;            // 0..31
    int sl = blockIdx.y;            // 0..7
    int b = bg >> 3, g = bg & 7;
    const float* base = x + (long)b * NPIX * CCH + g * GSIZE;
    float s = 0.f, ss = 0.f;
    for (int i = threadIdx.x; i < 512 * GSIZE; i += blockDim.x) {
        int p = sl * 512 + (i >> 5), c = i & 31;
        float v = base[(long)p * CCH + c];
        s += v; ss += v * v;
    }
    __shared__ float sh[16];
    #pragma unroll
    for (int o = 16; o > 0; o >>= 1) {
        s  += __shfl_xor_sync(0xffffffffu, s,  o);
        ss += __shfl_xor_sync(0xffffffffu, ss, o);
    }
    int w = threadIdx.x >> 5, l = threadIdx.x & 31;
    if (l == 0) { sh[w] = s; sh[8 + w] = ss; }
    __syncthreads();
    if (threadIdx.x == 0) {
        float S = 0.f, SS = 0.f;
        #pragma unroll
        for (int i = 0; i < 8; i++) { S += sh[i]; SS += sh[8 + i]; }
        g_ps [bg * 8 + sl] = S;
        g_ps2[bg * 8 + sl] = SS;
    }
}
__global__ void gn_final() {
    int bg = threadIdx.x;   // 32 threads
    float S = 0.f, SS = 0.f;
    #pragma unroll
    for (int i = 0; i < 8; i++) { S += g_ps[bg * 8 + i]; SS += g_ps2[bg * 8 + i]; }
    const float invn = 1.0f / (NPIX * GSIZE);
    float mean = S * invn;
    float var  = SS * invn - mean * mean;
    g_mean[bg] = mean;
    g_rstd[bg] = rsqrtf(var + 1e-3f);
}

// ---------------- GroupNorm apply: fp32 in, fp16 out ----------------
__global__ void gn_apply(const float* __restrict__ x,
                         const float* __restrict__ gamma,
                         const float* __restrict__ beta) {
    long i4 = (long)blockIdx.x * blockDim.x + threadIdx.x;   // float4 index
    float4 xv = ((const float4*)x)[i4];
    int c0 = (int)(i4 & 63) * 4;        // 64 float4 per channel row
    long row = i4 >> 6;                 // pixel index 0..16383
    int b = (int)(row >> 12);           // /4096
    int bg = b * 8 + (c0 >> 5);
    float m = g_mean[bg], r = g_rstd[bg];
    __half2 h0 = __floats2half2_rn((xv.x - m) * r * gamma[c0 + 0] + beta[c0 + 0],
                                   (xv.y - m) * r * gamma[c0 + 1] + beta[c0 + 1]);
    __half2 h1 = __floats2half2_rn((xv.z - m) * r * gamma[c0 + 2] + beta[c0 + 2],
                                   (xv.w - m) * r * gamma[c0 + 3] + beta[c0 + 3]);
    uint2 pk; pk.x = *(unsigned*)&h0; pk.y = *(unsigned*)&h1;
    ((uint2*)g_xnh)[i4] = pk;
}

// ---------------- transpose the four 256x256 weight matrices (fp16 out) ----------------
__global__ void transpose_w(const float* __restrict__ wq, const float* __restrict__ wk,
                            const float* __restrict__ wv, const float* __restrict__ wp) {
    __shared__ float t[32][33];
    int mat = blockIdx.z;
    const float* src = (mat == 0) ? wq : (mat == 1) ? wk : (mat == 2) ? wv : wp;
    int x0 = blockIdx.x * 32, y0 = blockIdx.y * 32;
    t[threadIdx.y][threadIdx.x] = src[(y0 + threadIdx.y) * CCH + x0 + threadIdx.x];
    __syncthreads();
    g_wTh[mat * CCH * CCH + (x0 + threadIdx.y) * CCH + y0 + threadIdx.x] =
        __float2half_rn(t[threadIdx.x][threadIdx.y]);
}

// ---------------- cp.async / mma / ldmatrix helpers ----------------
__device__ __forceinline__ void cp16g(void* smem, const void* gmem) {
    unsigned s = (unsigned)__cvta_generic_to_shared(smem);
    asm volatile("cp.async.cg.shared.global [%0], [%1], 16;\n" :: "r"(s), "l"(gmem));
}
__device__ __forceinline__ void cp_commit() { asm volatile("cp.async.commit_group;\n"); }
__device__ __forceinline__ void cp_wait0() { asm volatile("cp.async.wait_group 0;\n"); }
__device__ __forceinline__ void cp_wait1() { asm volatile("cp.async.wait_group 1;\n"); }

__device__ __forceinline__ void mma_f16(float* c, const unsigned* a, const unsigned* b) {
    asm volatile("mma.sync.aligned.m16n8k16.row.col.f32.f16.f16.f32 "
        "{%0,%1,%2,%3}, {%4,%5,%6,%7}, {%8,%9}, {%0,%1,%2,%3};"
        : "+f"(c[0]), "+f"(c[1]), "+f"(c[2]), "+f"(c[3])
        : "r"(a[0]), "r"(a[1]), "r"(a[2]), "r"(a[3]), "r"(b[0]), "r"(b[1]));
}
__device__ __forceinline__ void ldsm4(unsigned* r, uint32_t addr) {
    asm volatile("ldmatrix.sync.aligned.m8n8.x4.shared.b16 {%0,%1,%2,%3}, [%4];"
        : "=r"(r[0]), "=r"(r[1]), "=r"(r[2]), "=r"(r[3]) : "r"(addr));
}

// ================= unified fp16 GEMM: C = f(A @ B^T), CTA 128x128, warp 32x64 =================
// A: [M,K] halves lda, B: [N,K] halves ldb (dot over K). Batched via blockIdx.z.
// K-slab = 64 halves, smem pitch 72 halves (144 B), 3-stage cp.async pipeline,
// ONE __syncthreads per slab (loads for slab j+2 go to the stage freed at the
// top-of-loop barrier of slab j).
// EPI 0: C(half)  = acc + bias[col]; bias = biasc (z=0) or biasr (z=1)   (Q & K merged)
// EPI 1: C(half)  = acc + biasr[row]                                     (VT projection)
// EPI 2: C(half)  = exp(alpha*acc); Lp partial row sums                  (scores)
// EPI 3: C(half)  = acc * inv[row]                                       (attn @ V)
// EPI 4: C(float) = acc + biasc[col] + resid[off]                        (final projection)
#define HP 72                       // smem pitch in halves (64 data + 8 pad)
#define SSH (128 * HP)              // halves per matrix per stage (9216)
template<int EPI>
__global__ void __launch_bounds__(256, 2)
hgemm(const __half* __restrict__ A, int lda, long long sAz,
      const __half* __restrict__ B, int ldb, long long sBz,
      void* __restrict__ Cv, int ldc, long long sCz,
      const float* __restrict__ biasc, const float* __restrict__ biasr,
      const float* __restrict__ resid,
      float* __restrict__ Lp, const float* __restrict__ inv,
      float alpha, int K)
{
    extern __shared__ __align__(16) __half dsm[];   // [3][A:SSH | B:SSH]

    A += (long long)blockIdx.z * sAz;
    B += (long long)blockIdx.z * sBz;

    const int tid = threadIdx.x;
    const int w = tid >> 5, lane = tid & 31;
    const int gid = lane >> 2, tig = lane & 3;
    const int wm = (w & 3) * 32;        // 4 m-warps
    const int wn = (w >> 2) * 64;       // 2 n-warps
    const int wg = w >> 2;
    const long long m0 = (long long)blockIdx.y * 128;
    const long long n0 = (long long)blockIdx.x * 128;

    // loader coords: each thread copies 4x16B per matrix per stage
    const int lr = tid >> 1;            // row 0..127
    const int lc = (tid & 1) * 32;      // half-offset 0 or 32
    const __half* Ag = A + (m0 + lr) * lda + lc;
    const __half* Bg = B + (n0 + lr) * (long long)ldb + lc;
    __half* Asd = dsm + lr * HP + lc;   // stage 0 A dst

    // ldmatrix lane address components (in halves)
    const int a_row = wm + (lane & 15);
    const int a_col = (lane >> 4) << 3;
    const int b_row = wn + ((lane >> 4) << 3) + (lane & 7);
    const int b_col = ((lane >> 3) & 1) << 3;
    const uint32_t smB = (uint32_t)__cvta_generic_to_shared(dsm);

    float acc[2][8][4] = {};
    const int KT = K >> 6;              // slabs of 64 halves

    // prologue: slab 0 -> stage 0, slab 1 -> stage 1
    #pragma unroll
    for (int j = 0; j < 4; j++) { cp16g(Asd + 8 * j, Ag + 8 * j); }
    #pragma unroll
    for (int j = 0; j < 4; j++) { cp16g(Asd + SSH + 8 * j, Bg + 8 * j); }
    cp_commit();
    {
        __half* ad = Asd + 2 * SSH;
        #pragma unroll
        for (int j = 0; j < 4; j++) { cp16g(ad + 8 * j, Ag + 64 + 8 * j); }
        #pragma unroll
        for (int j = 0; j < 4; j++) { cp16g(ad + SSH + 8 * j, Bg + 64 + 8 * j); }
        cp_commit();
    }

    int sc = 0;                          // current stage = kt % 3
    for (int kt = 0; kt < KT; kt++) {
        if (kt + 1 < KT) cp_wait1(); else cp_wait0();
        __syncthreads();                 // stage sc ready; stage (kt+2)%3 free
        if (kt + 2 < KT) {
            int s2 = sc + 2; if (s2 >= 3) s2 -= 3;
            long long ko = (long long)(kt + 2) * 64;
            __half* ad = Asd + s2 * (2 * SSH);
            #pragma unroll
            for (int j = 0; j < 4; j++) { cp16g(ad + 8 * j, Ag + ko + 8 * j); }
            #pragma unroll
            for (int j = 0; j < 4; j++) { cp16g(ad + SSH + 8 * j, Bg + ko + 8 * j); }
            cp_commit();
        }
        const uint32_t asb = smB + sc * (4 * SSH);   // stage stride = 2*SSH halves = 4*SSH bytes
        const uint32_t bsb = asb + 2 * SSH;          // B offset = SSH halves = 2*SSH bytes
        #pragma unroll
        for (int kk = 0; kk < 64; kk += 16) {
            unsigned a[2][4], b[4][4];
            #pragma unroll
            for (int mt = 0; mt < 2; mt++)
                ldsm4(a[mt], asb + ((a_row + mt * 16) * HP + kk + a_col) * 2);
            #pragma unroll
            for (int p = 0; p < 4; p++)
                ldsm4(b[p], bsb + ((b_row + p * 16) * HP + kk + b_col) * 2);
            #pragma unroll
            for (int mt = 0; mt < 2; mt++)
                #pragma unroll
                for (int nt = 0; nt < 8; nt++)
                    mma_f16(acc[mt][nt], a[mt], &b[nt >> 1][(nt & 1) * 2]);
        }
        if (++sc == 3) sc = 0;
    }

    // ---------------- epilogue ----------------
    #pragma unroll
    for (int mt = 0; mt < 2; mt++) {
        #pragma unroll
        for (int h = 0; h < 2; h++) {
            long long row = m0 + wm + mt * 16 + gid + 8 * h;
            long long cbase = row * ldc + n0 + wn + 2 * tig;
            if (EPI == 2) {
                __half* C = (__half*)Cv + (long long)blockIdx.z * sCz;
                float rowsum = 0.f;
                #pragma unroll
                for (int nt = 0; nt < 8; nt++) {
                    float v0 = __expf(acc[mt][nt][2 * h]     * alpha);
                    float v1 = __expf(acc[mt][nt][2 * h + 1] * alpha);
                    rowsum += v0 + v1;
                    *(__half2*)&C[cbase + nt * 8] = __floats2half2_rn(v0, v1);
                }
                rowsum += __shfl_xor_sync(0xffffffffu, rowsum, 1);
                rowsum += __shfl_xor_sync(0xffffffffu, rowsum, 2);
                if (tig == 0)
                    Lp[(blockIdx.x * 2 + wg) * (long long)MALL
                       + blockIdx.z * (long long)NPIX + row] = rowsum;
            } else if (EPI == 3) {
                __half* C = (__half*)Cv + (long long)blockIdx.z * sCz;
                float rs = inv[blockIdx.z * (long long)NPIX + row];
                #pragma unroll
                for (int nt = 0; nt < 8; nt++)
                    *(__half2*)&C[cbase + nt * 8] =
                        __floats2half2_rn(acc[mt][nt][2 * h] * rs,
                                          acc[mt][nt][2 * h + 1] * rs);
            } else if (EPI == 4) {
                float* C = (float*)Cv;
                #pragma unroll
                for (int nt = 0; nt < 8; nt++) {
                    long long c0 = n0 + wn + nt * 8 + 2 * tig;
                    long long off = cbase + nt * 8;
                    float v0 = acc[mt][nt][2 * h]     + biasc[c0]     + resid[off];
                    float v1 = acc[mt][nt][2 * h + 1] + biasc[c0 + 1] + resid[off + 1];
                    *(float2*)&C[off] = make_float2(v0, v1);
                }
            } else if (EPI == 0) {
                __half* C = (__half*)Cv + (long long)blockIdx.z * sCz;
                const float* bc = blockIdx.z ? biasr : biasc;   // biasr slot carries bk
                #pragma unroll
                for (int nt = 0; nt < 8; nt++) {
                    long long c0 = n0 + wn + nt * 8 + 2 * tig;
                    *(__half2*)&C[cbase + nt * 8] =
                        __floats2half2_rn(acc[mt][nt][2 * h] + bc[c0],
                                          acc[mt][nt][2 * h + 1] + bc[c0 + 1]);
                }
            } else {  // EPI 1: row bias
                __half* C = (__half*)Cv;
                float rb = biasr[row];
                #pragma unroll
                for (int nt = 0; nt < 8; nt++)
                    *(__half2*)&C[cbase + nt * 8] =
                        __floats2half2_rn(acc[mt][nt][2 * h] + rb,
                                          acc[mt][nt][2 * h + 1] + rb);
            }
        }
    }
}

// ---------------- rowsum inverse: inv[i] = 1 / sum_j Lp[j][i] ----------------
__global__ void rowsum_inv(const float* __restrict__ Lp, float* __restrict__ inv) {
    int i = blockIdx.x * 256 + threadIdx.x;
    float s = 0.f;
    #pragma unroll
    for (int j = 0; j < 64; j++) s += Lp[j * MALL + i];
    inv[i] = 1.0f / s;
}

// ---------------- launch ----------------
extern "C" void kernel_launch(void* const* d_in, const int* in_sizes, int n_in,
                              void* d_out, int out_size) {
    const float* x     = (const float*)d_in[0];
    const float* gamma = (const float*)d_in[1];
    const float* beta  = (const float*)d_in[2];
    const float* wq    = (const float*)d_in[3];
    const float* bq    = (const float*)d_in[4];
    const float* wk    = (const float*)d_in[5];
    const float* bk    = (const float*)d_in[6];
    const float* wv    = (const float*)d_in[7];
    const float* bv    = (const float*)d_in[8];
    const float* wp    = (const float*)d_in[9];
    const float* bp    = (const float*)d_in[10];
    float* out = (float*)d_out;

    float *Lp, *inv;
    __half *xnh, *qkh, *vth, *oh, *sh, *wTh;
    cudaGetSymbolAddress((void**)&xnh, g_xnh);
    cudaGetSymbolAddress((void**)&qkh, g_qkh);
    cudaGetSymbolAddress((void**)&vth, g_vth);
    cudaGetSymbolAddress((void**)&oh,  g_oh);
    cudaGetSymbolAddress((void**)&sh,  g_sh);
    cudaGetSymbolAddress((void**)&wTh, g_wTh);
    cudaGetSymbolAddress((void**)&Lp,  g_Lp);
    cudaGetSymbolAddress((void**)&inv, g_inv);
    __half* qh = qkh;
    __half* kh = qkh + (long long)MALL * CCH;

    const int SMB = 3 * 2 * SSH * 2;   // 110,592 B dynamic smem (occ 2 = 221 KB/SM)
    cudaFuncSetAttribute(hgemm<0>, cudaFuncAttributeMaxDynamicSharedMemorySize, SMB);
    cudaFuncSetAttribute(hgemm<1>, cudaFuncAttributeMaxDynamicSharedMemorySize, SMB);
    cudaFuncSetAttribute(hgemm<2>, cudaFuncAttributeMaxDynamicSharedMemorySize, SMB);
    cudaFuncSetAttribute(hgemm<3>, cudaFuncAttributeMaxDynamicSharedMemorySize, SMB);
    cudaFuncSetAttribute(hgemm<4>, cudaFuncAttributeMaxDynamicSharedMemorySize, SMB);

    // 1. GroupNorm -> fp16 xn
    gn_part<<<dim3(BATCH * GRP, 8), 256>>>(x);
    gn_final<<<1, 32>>>();
    gn_apply<<<(MALL * CCH / 4) / 256, 256>>>(x, gamma, beta);

    // 2. transpose weights -> fp16
    transpose_w<<<dim3(8, 8, 4), dim3(32, 32)>>>(wq, wk, wv, wp);

    // 3. Q & K (merged, grid.z selects), VT (produced transposed)
    hgemm<0><<<dim3(2, 128, 2), 256, SMB>>>(
        xnh, CCH, 0, wTh, CCH, (long long)CCH * CCH, qkh, CCH, (long long)MALL * CCH,
        bq, bk, nullptr, nullptr, nullptr, 1.0f, CCH);
    hgemm<1><<<dim3(MALL / 128, CCH / 128, 1), 256, SMB>>>(
        wTh + 2 * CCH * CCH, CCH, 0, xnh, CCH, 0, vth, MALL, 0,
        nullptr, bv, nullptr, nullptr, nullptr, 1.0f, CCH);

    // 4. S = exp(Q @ K^T / 16) in fp16, plus row-sum partials
    hgemm<2><<<dim3(NPIX / 128, NPIX / 128, BATCH), 256, SMB>>>(
        qh, CCH, (long long)NPIX * CCH,
        kh, CCH, (long long)NPIX * CCH,
        sh, NPIX, (long long)NPIX * NPIX,
        nullptr, nullptr, nullptr, Lp, nullptr, 0.0625f, CCH);

    // 5. inv[row] = 1 / rowsum
    rowsum_inv<<<MALL / 256, 256>>>(Lp, inv);

    // 6. O = (S @ V) * inv  -> fp16   (K = 4096)
    hgemm<3><<<dim3(CCH / 128, NPIX / 128, BATCH), 256, SMB>>>(
        sh, NPIX, (long long)NPIX * NPIX,
        vth, MALL, (long long)NPIX,
        oh, CCH, (long long)NPIX * CCH,
        nullptr, nullptr, nullptr, nullptr, inv, 1.0f, NPIX);

    // 7. y = x + O @ wp + bp   (fp32 out)
    hgemm<4><<<dim3(2, 128, 1), 256, SMB>>>(
        oh, CCH, 0, wTh + 3 * CCH * CCH, CCH, 0, out, CCH, 0,
        bp, nullptr, x, nullptr, nullptr, 1.0f, CCH);
}